// round 3
// baseline (speedup 1.0000x reference)
#include <cuda_runtime.h>
#include <cstdint>

#define BB 8
#define NN 512
#define DD 768
#define HSZ 64
#define TOK (BB*NN)        // 4096
#define HDIM 384           // 3 * 128
#define NEGF 1e12f

// ---------------- scratch (no allocs allowed) ----------------
__device__ float g_h[TOK*HDIM];              // 6.3 MB: h rows for 3 types
__device__ float g_q[3][BB][NN][HSZ];        // q (scaled by 1/8, rope'd for ent)
__device__ float g_k[3][BB][NN][HSZ];
__device__ float g_bias[3][BB][24][NN];      // [type][b][j][n], j<2*heads, already /2

// =============================================================
// Kernel 1: h_all(4096,384) = X(4096,768) @ W_all^T + b1
// 64x64 tiles, 4x4 per thread, K chunks of 16.
// =============================================================
__global__ __launch_bounds__(256) void k1_gemm(
    const float* __restrict__ X,
    const float* __restrict__ w1e, const float* __restrict__ b1e,
    const float* __restrict__ w1h, const float* __restrict__ b1h,
    const float* __restrict__ w1t, const float* __restrict__ b1t)
{
    __shared__ float xs[16][68];
    __shared__ float ws[16][68];

    const int ntile = blockIdx.x;          // 0..5
    const int mtile = blockIdx.y;          // 0..63
    const int type  = ntile >> 1;
    const float* W  = (type==0) ? w1e : (type==1) ? w1h : w1t;
    const float* bb = (type==0) ? b1e : (type==1) ? b1h : b1t;
    const int nloc0 = (ntile & 1) * 64;    // offset within the 128-wide branch
    const int m0    = mtile * 64;

    const int tid  = threadIdx.x;
    const int tx   = tid & 15;
    const int ty   = tid >> 4;
    const int lrow = tid >> 2;             // 0..63
    const int lc4  = (tid & 3) * 4;        // 0,4,8,12

    float acc[4][4] = {};
    const float* xg = X + (size_t)(m0 + lrow) * DD + lc4;
    const float* wg = W + (size_t)(nloc0 + lrow) * DD + lc4;

    for (int k0 = 0; k0 < DD; k0 += 16) {
        float4 xa = *(const float4*)(xg + k0);
        float4 wa = *(const float4*)(wg + k0);
        __syncthreads();
        xs[lc4+0][lrow]=xa.x; xs[lc4+1][lrow]=xa.y; xs[lc4+2][lrow]=xa.z; xs[lc4+3][lrow]=xa.w;
        ws[lc4+0][lrow]=wa.x; ws[lc4+1][lrow]=wa.y; ws[lc4+2][lrow]=wa.z; ws[lc4+3][lrow]=wa.w;
        __syncthreads();
        #pragma unroll
        for (int kk = 0; kk < 16; kk++) {
            float4 a  = *(const float4*)&xs[kk][ty*4];
            float4 b4 = *(const float4*)&ws[kk][tx*4];
            float av[4] = {a.x, a.y, a.z, a.w};
            float bv[4] = {b4.x, b4.y, b4.z, b4.w};
            #pragma unroll
            for (int i = 0; i < 4; i++)
                #pragma unroll
                for (int j = 0; j < 4; j++)
                    acc[i][j] += av[i] * bv[j];
        }
    }

    const int ng0 = ntile * 64;
    #pragma unroll
    for (int i = 0; i < 4; i++) {
        const int m = m0 + ty*4 + i;
        #pragma unroll
        for (int j = 0; j < 4; j++) {
            const int nl = nloc0 + tx*4 + j;
            g_h[(size_t)m * HDIM + ng0 + tx*4 + j] = acc[i][j] + bb[nl];
        }
    }
}

// =============================================================
// Kernel 2: per-token prep.
//  - q/k deinterleave (rope for entity), q scaled by 1/8
//  - bias[type][b][j][n] = (h . w2[j] + b2[j]) / 2
// 8 tokens per block, 128 threads.
// =============================================================
#define TPB2 8
__global__ __launch_bounds__(128) void k2_prep(
    const float* __restrict__ w2e, const float* __restrict__ b2e,
    const float* __restrict__ w2h, const float* __restrict__ b2h,
    const float* __restrict__ w2t, const float* __restrict__ b2t)
{
    __shared__ float hrow[TPB2][HDIM];
    __shared__ float w2s[52][129];
    __shared__ float b2s[52];

    const int t0  = blockIdx.x * TPB2;
    const int tid = threadIdx.x;

    // stage all w2 rows: 0..3 ent, 4..27 head, 28..51 tail
    for (int f = tid; f < 52*128; f += 128) {
        const int r = f >> 7, e = f & 127;
        const float* src = (r < 4)  ? (w2e + r*128)
                         : (r < 28) ? (w2h + (r-4)*128)
                                    : (w2t + (r-28)*128);
        w2s[r][e] = src[e];
    }
    if (tid < 52)
        b2s[tid] = (tid < 4) ? b2e[tid] : (tid < 28) ? b2h[tid-4] : b2t[tid-28];

    // stage 8 h rows (contiguous)
    for (int f = tid; f < TPB2*HDIM; f += 128)
        ((float*)hrow)[f] = g_h[(size_t)t0*HDIM + f];
    __syncthreads();

    for (int tt = 0; tt < TPB2; tt++) {
        const int tok = t0 + tt;
        const int b = tok >> 9, n = tok & 511;

        // q/k for 3 types
        for (int idx = tid; idx < 192; idx += 128) {
            const int ty = idx >> 6, e = idx & 63;
            float qv = hrow[tt][ty*128 + 2*e];
            float kv = hrow[tt][ty*128 + 2*e + 1];
            if (ty == 0) {
                const int i = e >> 1;
                const float inv = powf(10000.0f, -(float)i / 32.0f);
                const float ang = (float)n * inv;
                const float c = cosf(ang), s = sinf(ang);
                const int pe = (e & 1) ? (e - 1) : (e + 1);   // partner element
                const float qp = hrow[tt][2*pe];
                const float kp = hrow[tt][2*pe + 1];
                const float sgn = (e & 1) ? 1.0f : -1.0f;
                qv = qv*c + sgn*qp*s;
                kv = kv*c + sgn*kp*s;
            }
            g_q[ty][b][n][e] = qv * 0.125f;
            g_k[ty][b][n][e] = kv;
        }

        // bias GEMV: 52 outputs, K=128
        if (tid < 52) {
            const int base = (tid < 4) ? 0 : (tid < 28) ? 128 : 256;
            const float* hb = &hrow[tt][base];
            float acc = 0.0f;
            #pragma unroll 16
            for (int e = 0; e < 128; e++)
                acc += hb[e] * w2s[tid][e];
            const int ty = (tid < 4) ? 0 : (tid < 28) ? 1 : 2;
            const int j  = (tid < 4) ? tid : (tid < 28) ? tid-4 : tid-28;
            g_bias[ty][b][j][n] = (acc + b2s[tid]) * 0.5f;
        }
    }
}

// =============================================================
// Kernel 3: per (b, 64x64 tile): compute 3 logits tiles once,
// fan out 26 head planes with bias broadcast + pad/tril masks.
// =============================================================
__global__ __launch_bounds__(256) void k3_out(
    const int* __restrict__ mask, float* __restrict__ out)
{
    __shared__ float qs[64][68];
    __shared__ float ks[64][68];
    __shared__ int   mms[64];
    __shared__ int   mns[64];

    const int n0 = blockIdx.x * 64;
    const int m0 = blockIdx.y * 64;
    const int b  = blockIdx.z;
    const int tid = threadIdx.x;
    const int tx = tid & 15;
    const int ty = tid >> 4;
    const int lrow = tid >> 2;
    const int lc   = (tid & 3) * 16;

    if (tid < 64)       mms[tid]      = mask[b*NN + m0 + tid];
    else if (tid < 128) mns[tid - 64] = mask[b*NN + n0 + tid - 64];

    const size_t ENT_SZ = (size_t)BB * 2  * NN * NN;   // 4,194,304
    const size_t HT_SZ  = (size_t)BB * 12 * NN * NN;   // 25,165,824
    (void)HT_SZ;

    for (int t = 0; t < 3; t++) {
        __syncthreads();   // also covers mask stores on first pass
        #pragma unroll
        for (int v = 0; v < 4; v++) {
            const int kk = lc + v*4;
            float4 qa = *(const float4*)&g_q[t][b][m0 + lrow][kk];
            float4 ka = *(const float4*)&g_k[t][b][n0 + lrow][kk];
            qs[kk+0][lrow]=qa.x; qs[kk+1][lrow]=qa.y; qs[kk+2][lrow]=qa.z; qs[kk+3][lrow]=qa.w;
            ks[kk+0][lrow]=ka.x; ks[kk+1][lrow]=ka.y; ks[kk+2][lrow]=ka.z; ks[kk+3][lrow]=ka.w;
        }
        __syncthreads();

        float acc[4][4] = {};
        #pragma unroll
        for (int kk = 0; kk < 64; kk++) {
            float4 a  = *(const float4*)&qs[kk][ty*4];
            float4 b4 = *(const float4*)&ks[kk][tx*4];
            float av[4] = {a.x, a.y, a.z, a.w};
            float bv[4] = {b4.x, b4.y, b4.z, b4.w};
            #pragma unroll
            for (int i = 0; i < 4; i++)
                #pragma unroll
                for (int j = 0; j < 4; j++)
                    acc[i][j] += av[i] * bv[j];
        }

        const int H = (t == 0) ? 2 : 12;
        const size_t base = (t == 0) ? 0
                          : (t == 1) ? ENT_SZ
                                     : ENT_SZ + (size_t)BB*12*NN*NN;
        const int mloc = ty*4, nloc = tx*4;

        int mi[4], nj[4];
        #pragma unroll
        for (int i = 0; i < 4; i++) mi[i] = mms[mloc + i];
        #pragma unroll
        for (int j = 0; j < 4; j++) nj[j] = mns[nloc + j];

        for (int hd = 0; hd < H; hd++) {
            float4 bev = __ldg((const float4*)&g_bias[t][b][2*hd][n0 + nloc]);
            const float beo[4] = {bev.x, bev.y, bev.z, bev.w};
            float boi[4];
            #pragma unroll
            for (int i = 0; i < 4; i++)
                boi[i] = __ldg(&g_bias[t][b][2*hd + 1][m0 + mloc + i]);

            float* op = out + base
                      + (((size_t)(b*H + hd)) * NN + (m0 + mloc)) * NN
                      + n0 + nloc;
            #pragma unroll
            for (int i = 0; i < 4; i++) {
                float4 o;
                float* oo = &o.x;
                #pragma unroll
                for (int j = 0; j < 4; j++) {
                    float v = acc[i][j] + beo[j] + boi[i];
                    float sub = 0.0f;
                    if (!(mi[i] & nj[j])) sub = NEGF;
                    if (t == 0 && (m0 + mloc + i) > (n0 + nloc + j)) sub += NEGF;
                    oo[j] = v - sub;
                }
                *(float4*)(op + (size_t)i * NN) = o;
            }
        }
    }
}

// =============================================================
extern "C" void kernel_launch(void* const* d_in, const int* in_sizes, int n_in,
                              void* d_out, int out_size)
{
    (void)in_sizes; (void)n_in; (void)out_size;
    const float* chars = (const float*)d_in[0];
    const int*   mask  = (const int*)  d_in[1];
    const float* w1e = (const float*)d_in[2];
    const float* b1e = (const float*)d_in[3];
    const float* w2e = (const float*)d_in[4];
    const float* b2e = (const float*)d_in[5];
    const float* w1h = (const float*)d_in[6];
    const float* b1h = (const float*)d_in[7];
    const float* w2h = (const float*)d_in[8];
    const float* b2h = (const float*)d_in[9];
    const float* w1t = (const float*)d_in[10];
    const float* b1t = (const float*)d_in[11];
    const float* w2t = (const float*)d_in[12];
    const float* b2t = (const float*)d_in[13];
    float* out = (float*)d_out;

    dim3 g1(6, 64);
    k1_gemm<<<g1, 256>>>(chars, w1e, b1e, w1h, b1h, w1t, b1t);

    k2_prep<<<TOK / TPB2, 128>>>(w2e, b2e, w2h, b2h, w2t, b2t);

    dim3 g3(8, 8, 8);
    k3_out<<<g3, 256>>>(mask, out);
}

// round 7
// speedup vs baseline: 1.8465x; 1.8465x over previous
#include <cuda_runtime.h>
#include <cuda_bf16.h>
#include <cstdint>

#define BB 8
#define NN 512
#define DD 768
#define HSZ 64
#define TOK (BB*NN)        // 4096
#define HDIM 384           // 3 * 128
#define NEGF 1e12f

// ---------------- scratch (no allocs allowed) ----------------
__device__ float g_h[TOK*HDIM];                   // h rows for 3 types
__device__ __nv_bfloat16 g_xb[TOK*DD];            // chars in bf16
__device__ __nv_bfloat16 g_wb[HDIM*DD];           // w1 (ent|head|tail) in bf16
__device__ float g_q[3][BB][NN][HSZ];
__device__ float g_k[3][BB][NN][HSZ];
__device__ float g_bias[3][BB][24][NN];

__device__ __forceinline__ uint32_t smem_u32(const void* p) {
    uint32_t a;
    asm("{ .reg .u64 t; cvta.to.shared.u64 t, %1; cvt.u32.u64 %0, t; }" : "=r"(a) : "l"(p));
    return a;
}
__device__ __forceinline__ uint32_t sw128(uint32_t off) {
    return off ^ ((off >> 3) & 0x70);
}
__device__ __forceinline__ void ldmx4(uint32_t* r, uint32_t addr) {
    asm volatile("ldmatrix.sync.aligned.m8n8.x4.shared.b16 {%0,%1,%2,%3}, [%4];"
                 : "=r"(r[0]), "=r"(r[1]), "=r"(r[2]), "=r"(r[3]) : "r"(addr));
}
__device__ __forceinline__ void mma_bf16(float* d, const uint32_t* a, const uint32_t* b) {
    asm volatile(
        "mma.sync.aligned.m16n8k16.row.col.f32.bf16.bf16.f32 "
        "{%0,%1,%2,%3}, {%4,%5,%6,%7}, {%8,%9}, {%0,%1,%2,%3};"
        : "+f"(d[0]), "+f"(d[1]), "+f"(d[2]), "+f"(d[3])
        : "r"(a[0]), "r"(a[1]), "r"(a[2]), "r"(a[3]), "r"(b[0]), "r"(b[1]));
}

// =============================================================
// Kernel 0: fp32 -> bf16 convert for X and W1(ent|head|tail)
// =============================================================
#define XT_GROUPS (TOK*DD/8)      // 393216
#define WT_GROUPS (HDIM*DD/8)     // 36864
__global__ __launch_bounds__(256) void k0_convert(
    const float* __restrict__ X,
    const float* __restrict__ w1e, const float* __restrict__ w1h,
    const float* __restrict__ w1t)
{
    const int i = blockIdx.x * 256 + threadIdx.x;
    if (i >= XT_GROUPS + WT_GROUPS) return;
    const float* src;
    __nv_bfloat16* dst;
    if (i < XT_GROUPS) {
        src = X + (size_t)i * 8;
        dst = g_xb + (size_t)i * 8;
    } else {
        const int j = i - XT_GROUPS;
        const int n = (j * 8) / DD;
        const int col = (j * 8) % DD;
        const int br = n >> 7, nl = n & 127;
        const float* w = (br == 0) ? w1e : (br == 1) ? w1h : w1t;
        src = w + (size_t)nl * DD + col;
        dst = g_wb + (size_t)n * DD + col;
    }
    float4 a = *(const float4*)src;
    float4 b = *(const float4*)(src + 4);
    __nv_bfloat162 p0 = __floats2bfloat162_rn(a.x, a.y);
    __nv_bfloat162 p1 = __floats2bfloat162_rn(a.z, a.w);
    __nv_bfloat162 p2 = __floats2bfloat162_rn(b.x, b.y);
    __nv_bfloat162 p3 = __floats2bfloat162_rn(b.z, b.w);
    uint4 r;
    r.x = *(uint32_t*)&p0; r.y = *(uint32_t*)&p1;
    r.z = *(uint32_t*)&p2; r.w = *(uint32_t*)&p3;
    *(uint4*)dst = r;
}

// =============================================================
// Kernel 1: h = X @ W1^T + b1 via mma.sync bf16 (HMMA).
// CTA tile 64m x 64n, 4 warps (2x2), warp tile 32x32.
// K = 768 in 12 chunks of 64, SW128 smem, reg-prefetch pipeline.
// =============================================================
__global__ __launch_bounds__(128) void k1_mma(
    const float* __restrict__ b1e, const float* __restrict__ b1h,
    const float* __restrict__ b1t)
{
    __shared__ __align__(128) uint8_t sA[64 * 128];   // 64 rows x 64 bf16
    __shared__ __align__(128) uint8_t sB[64 * 128];

    const int tid  = threadIdx.x;
    const int lane = tid & 31;
    const int wid  = tid >> 5;
    const int nt = blockIdx.x;            // 0..5
    const int mt = blockIdx.y;            // 0..63
    const int m0 = mt * 64;
    const int nbr = nt >> 1;              // branch
    const int nl0 = (nt & 1) * 64;        // col offset within branch
    const int mw = (wid >> 1) * 32;
    const int nw = (wid & 1) * 32;
    const uint32_t sa = smem_u32(sA);
    const uint32_t sb = smem_u32(sB);

    // per-thread load/store mapping: lin = i*128 + tid; row = lin>>3, chunk = lin&7
    const int lrow = tid >> 3;            // +16 per i
    const int lch  = tid & 7;

    float acc[2][4][4] = {};

    uint4 ar[4], br[4];
    // prefetch chunk 0
    {
        const __nv_bfloat16* ag = g_xb + (size_t)(m0 + lrow) * DD + lch * 8;
        const __nv_bfloat16* bg = g_wb + (size_t)(nt * 64 + lrow) * DD + lch * 8;
        #pragma unroll
        for (int i = 0; i < 4; i++) {
            ar[i] = *(const uint4*)(ag + (size_t)i * 16 * DD);
            br[i] = *(const uint4*)(bg + (size_t)i * 16 * DD);
        }
    }

    for (int c = 0; c < 12; c++) {
        __syncthreads();
        #pragma unroll
        for (int i = 0; i < 4; i++) {
            const uint32_t bo = sw128((lrow + i * 16) * 128 + lch * 16);
            *(uint4*)(sA + bo) = ar[i];
            *(uint4*)(sB + bo) = br[i];
        }
        __syncthreads();
        if (c < 11) {
            const int cc = c + 1;
            const __nv_bfloat16* ag = g_xb + (size_t)(m0 + lrow) * DD + cc * 64 + lch * 8;
            const __nv_bfloat16* bg = g_wb + (size_t)(nt * 64 + lrow) * DD + cc * 64 + lch * 8;
            #pragma unroll
            for (int i = 0; i < 4; i++) {
                ar[i] = *(const uint4*)(ag + (size_t)i * 16 * DD);
                br[i] = *(const uint4*)(bg + (size_t)i * 16 * DD);
            }
        }
        #pragma unroll
        for (int ks = 0; ks < 4; ks++) {
            const int kb = ks * 32;   // byte offset within 128B row
            uint32_t afr[2][4];
            #pragma unroll
            for (int f = 0; f < 2; f++) {
                const int row = mw + f * 16 + (lane & 15);
                const uint32_t addr = sa + sw128(row * 128 + kb + ((lane >> 4) << 4));
                ldmx4(afr[f], addr);
            }
            uint32_t bfr[4][2];
            #pragma unroll
            for (int g2 = 0; g2 < 2; g2++) {
                const int sel = lane >> 3;
                const int row = nw + g2 * 16 + ((sel & 2) ? 8 : 0) + (lane & 7);
                const uint32_t addr = sb + sw128(row * 128 + kb + ((sel & 1) << 4));
                uint32_t t[4];
                ldmx4(t, addr);
                bfr[g2 * 2 + 0][0] = t[0]; bfr[g2 * 2 + 0][1] = t[1];
                bfr[g2 * 2 + 1][0] = t[2]; bfr[g2 * 2 + 1][1] = t[3];
            }
            #pragma unroll
            for (int f = 0; f < 2; f++)
                #pragma unroll
                for (int g = 0; g < 4; g++)
                    mma_bf16(acc[f][g], afr[f], bfr[g]);
        }
    }

    // epilogue: fragments -> g_h with bias (fp32)
    const float* b1 = (nbr == 0) ? b1e : (nbr == 1) ? b1h : b1t;
    #pragma unroll
    for (int f = 0; f < 2; f++) {
        const int mrow = m0 + mw + f * 16 + (lane >> 2);
        #pragma unroll
        for (int g = 0; g < 4; g++) {
            const int nloc = nw + g * 8 + (lane & 3) * 2;
            const float bx = b1[nl0 + nloc], by = b1[nl0 + nloc + 1];
            float2 v0 = { acc[f][g][0] + bx, acc[f][g][1] + by };
            float2 v1 = { acc[f][g][2] + bx, acc[f][g][3] + by };
            *(float2*)&g_h[(size_t)mrow * HDIM + nt * 64 + nloc] = v0;
            *(float2*)&g_h[(size_t)(mrow + 8) * HDIM + nt * 64 + nloc] = v1;
        }
    }
}

// =============================================================
// Kernel 2: per-token prep (q/k deinterleave + RoPE, bias GEMV)
// =============================================================
#define TPB2 8
__global__ __launch_bounds__(128) void k2_prep(
    const float* __restrict__ w2e, const float* __restrict__ b2e,
    const float* __restrict__ w2h, const float* __restrict__ b2h,
    const float* __restrict__ w2t, const float* __restrict__ b2t)
{
    __shared__ float hrow[TPB2][HDIM];
    __shared__ float w2s[52][129];
    __shared__ float b2s[52];

    const int t0  = blockIdx.x * TPB2;
    const int tid = threadIdx.x;

    for (int f = tid; f < 52*128; f += 128) {
        const int r = f >> 7, e = f & 127;
        const float* src = (r < 4)  ? (w2e + r*128)
                         : (r < 28) ? (w2h + (r-4)*128)
                                    : (w2t + (r-28)*128);
        w2s[r][e] = src[e];
    }
    if (tid < 52)
        b2s[tid] = (tid < 4) ? b2e[tid] : (tid < 28) ? b2h[tid-4] : b2t[tid-28];

    for (int f = tid; f < TPB2*HDIM; f += 128)
        ((float*)hrow)[f] = g_h[(size_t)t0*HDIM + f];
    __syncthreads();

    for (int tt = 0; tt < TPB2; tt++) {
        const int tok = t0 + tt;
        const int b = tok >> 9, n = tok & 511;

        for (int idx = tid; idx < 192; idx += 128) {
            const int ty = idx >> 6, e = idx & 63;
            float qv = hrow[tt][ty*128 + 2*e];
            float kv = hrow[tt][ty*128 + 2*e + 1];
            if (ty == 0) {
                const int i = e >> 1;
                const float inv = powf(10000.0f, -(float)i / 32.0f);
                const float ang = (float)n * inv;
                const float c = cosf(ang), s = sinf(ang);
                const int pe = (e & 1) ? (e - 1) : (e + 1);
                const float qp = hrow[tt][2*pe];
                const float kp = hrow[tt][2*pe + 1];
                const float sgn = (e & 1) ? 1.0f : -1.0f;
                qv = qv*c + sgn*qp*s;
                kv = kv*c + sgn*kp*s;
            }
            g_q[ty][b][n][e] = qv * 0.125f;
            g_k[ty][b][n][e] = kv;
        }

        if (tid < 52) {
            const int base = (tid < 4) ? 0 : (tid < 28) ? 128 : 256;
            const float* hb = &hrow[tt][base];
            float acc = 0.0f;
            #pragma unroll 16
            for (int e = 0; e < 128; e++)
                acc += hb[e] * w2s[tid][e];
            const int ty = (tid < 4) ? 0 : (tid < 28) ? 1 : 2;
            const int j  = (tid < 4) ? tid : (tid < 28) ? tid-4 : tid-28;
            g_bias[ty][b][j][n] = (acc + b2s[tid]) * 0.5f;
        }
    }
}

// =============================================================
// Kernel 3: per (b, 64x64 tile): compute 3 logits tiles once,
// fan out 26 head planes. Bias staged in smem, streaming stores.
// =============================================================
__global__ __launch_bounds__(256) void k3_out(
    const int* __restrict__ mask, float* __restrict__ out)
{
    __shared__ float qs[64][68];
    __shared__ float ks[64][68];
    __shared__ float bse[12][68];
    __shared__ float bso[12][68];
    __shared__ int   mms[64];
    __shared__ int   mns[64];

    const int n0 = blockIdx.x * 64;
    const int m0 = blockIdx.y * 64;
    const int b  = blockIdx.z;
    const int tid = threadIdx.x;
    const int tx = tid & 15;
    const int ty = tid >> 4;
    const int lrow = tid >> 2;
    const int lc   = (tid & 3) * 16;

    if (tid < 64)       mms[tid]      = mask[b*NN + m0 + tid];
    else if (tid < 128) mns[tid - 64] = mask[b*NN + n0 + tid - 64];

    const size_t ENT_SZ = (size_t)BB * 2  * NN * NN;

    for (int t = 0; t < 3; t++) {
        const int H = (t == 0) ? 2 : 12;
        __syncthreads();
        #pragma unroll
        for (int v = 0; v < 4; v++) {
            const int kk = lc + v*4;
            float4 qa = *(const float4*)&g_q[t][b][m0 + lrow][kk];
            float4 ka = *(const float4*)&g_k[t][b][n0 + lrow][kk];
            qs[kk+0][lrow]=qa.x; qs[kk+1][lrow]=qa.y; qs[kk+2][lrow]=qa.z; qs[kk+3][lrow]=qa.w;
            ks[kk+0][lrow]=ka.x; ks[kk+1][lrow]=ka.y; ks[kk+2][lrow]=ka.z; ks[kk+3][lrow]=ka.w;
        }
        for (int f = tid; f < H*64; f += 256) {
            const int hd = f >> 6, e = f & 63;
            bse[hd][e] = g_bias[t][b][2*hd][n0 + e];
            bso[hd][e] = g_bias[t][b][2*hd + 1][m0 + e];
        }
        __syncthreads();

        float acc[4][4] = {};
        #pragma unroll
        for (int kk = 0; kk < 64; kk++) {
            float4 a  = *(const float4*)&qs[kk][ty*4];
            float4 b4 = *(const float4*)&ks[kk][tx*4];
            float av[4] = {a.x, a.y, a.z, a.w};
            float bv[4] = {b4.x, b4.y, b4.z, b4.w};
            #pragma unroll
            for (int i = 0; i < 4; i++)
                #pragma unroll
                for (int j = 0; j < 4; j++)
                    acc[i][j] += av[i] * bv[j];
        }

        const size_t base = (t == 0) ? 0
                          : (t == 1) ? ENT_SZ
                                     : ENT_SZ + (size_t)BB*12*NN*NN;
        const int mloc = ty*4, nloc = tx*4;

        int mi[4], nj[4];
        #pragma unroll
        for (int i = 0; i < 4; i++) mi[i] = mms[mloc + i];
        #pragma unroll
        for (int j = 0; j < 4; j++) nj[j] = mns[nloc + j];

        for (int hd = 0; hd < H; hd++) {
            float4 bev = *(const float4*)&bse[hd][nloc];
            const float beo[4] = {bev.x, bev.y, bev.z, bev.w};
            float boi[4];
            #pragma unroll
            for (int i = 0; i < 4; i++)
                boi[i] = bso[hd][mloc + i];

            float* op = out + base
                      + (((size_t)(b*H + hd)) * NN + (m0 + mloc)) * NN
                      + n0 + nloc;
            #pragma unroll
            for (int i = 0; i < 4; i++) {
                float4 o;
                float* oo = &o.x;
                #pragma unroll
                for (int j = 0; j < 4; j++) {
                    float v = acc[i][j] + beo[j] + boi[i];
                    float sub = 0.0f;
                    if (!(mi[i] & nj[j])) sub = NEGF;
                    if (t == 0 && (m0 + mloc + i) > (n0 + nloc + j)) sub += NEGF;
                    oo[j] = v - sub;
                }
                __stcs((float4*)(op + (size_t)i * NN), o);
            }
        }
    }
}

// =============================================================
extern "C" void kernel_launch(void* const* d_in, const int* in_sizes, int n_in,
                              void* d_out, int out_size)
{
    (void)in_sizes; (void)n_in; (void)out_size;
    const float* chars = (const float*)d_in[0];
    const int*   mask  = (const int*)  d_in[1];
    const float* w1e = (const float*)d_in[2];
    const float* b1e = (const float*)d_in[3];
    const float* w2e = (const float*)d_in[4];
    const float* b2e = (const float*)d_in[5];
    const float* w1h = (const float*)d_in[6];
    const float* b1h = (const float*)d_in[7];
    const float* w2h = (const float*)d_in[8];
    const float* b2h = (const float*)d_in[9];
    const float* w1t = (const float*)d_in[10];
    const float* b1t = (const float*)d_in[11];
    const float* w2t = (const float*)d_in[12];
    const float* b2t = (const float*)d_in[13];
    float* out = (float*)d_out;

    const int cvt_groups = XT_GROUPS + WT_GROUPS;
    k0_convert<<<(cvt_groups + 255) / 256, 256>>>(chars, w1e, w1h, w1t);

    dim3 g1(6, 64);
    k1_mma<<<g1, 128>>>(b1e, b1h, b1t);

    k2_prep<<<TOK / TPB2, 128>>>(w2e, b2e, w2h, b2h, w2t, b2t);

    dim3 g3(8, 8, 8);
    k3_out<<<g3, 256>>>(mask, out);
}

// round 8
// speedup vs baseline: 2.3186x; 1.2557x over previous
#include <cuda_runtime.h>
#include <cuda_bf16.h>
#include <cstdint>

#define BB 8
#define NN 512
#define DD 768
#define HSZ 64
#define TOK (BB*NN)        // 4096
#define HDIM 384           // 3 * 128
#define NEGF 1e12f

// ---------------- scratch (no allocs allowed) ----------------
__device__ float g_h[TOK*HDIM];                   // h rows for 3 types
__device__ __nv_bfloat16 g_xb[TOK*DD];            // chars in bf16
__device__ __nv_bfloat16 g_wb[HDIM*DD];           // w1 (ent|head|tail) in bf16
__device__ __nv_bfloat16 g_q[3][BB][NN][HSZ];     // bf16 q (scaled 1/8, rope'd)
__device__ __nv_bfloat16 g_k[3][BB][NN][HSZ];     // bf16 k
__device__ float g_bias[3][BB][24][NN];

__device__ __forceinline__ uint32_t smem_u32(const void* p) {
    uint32_t a;
    asm("{ .reg .u64 t; cvta.to.shared.u64 t, %1; cvt.u32.u64 %0, t; }" : "=r"(a) : "l"(p));
    return a;
}
__device__ __forceinline__ uint32_t sw128(uint32_t off) {
    return off ^ ((off >> 3) & 0x70);
}
__device__ __forceinline__ void ldmx4(uint32_t* r, uint32_t addr) {
    asm volatile("ldmatrix.sync.aligned.m8n8.x4.shared.b16 {%0,%1,%2,%3}, [%4];"
                 : "=r"(r[0]), "=r"(r[1]), "=r"(r[2]), "=r"(r[3]) : "r"(addr));
}
__device__ __forceinline__ void mma_bf16(float* d, const uint32_t* a, const uint32_t* b) {
    asm volatile(
        "mma.sync.aligned.m16n8k16.row.col.f32.bf16.bf16.f32 "
        "{%0,%1,%2,%3}, {%4,%5,%6,%7}, {%8,%9}, {%0,%1,%2,%3};"
        : "+f"(d[0]), "+f"(d[1]), "+f"(d[2]), "+f"(d[3])
        : "r"(a[0]), "r"(a[1]), "r"(a[2]), "r"(a[3]), "r"(b[0]), "r"(b[1]));
}

// =============================================================
// Kernel 0: fp32 -> bf16 convert for X and W1(ent|head|tail)
// =============================================================
#define XT_GROUPS (TOK*DD/8)      // 393216
#define WT_GROUPS (HDIM*DD/8)     // 36864
__global__ __launch_bounds__(256) void k0_convert(
    const float* __restrict__ X,
    const float* __restrict__ w1e, const float* __restrict__ w1h,
    const float* __restrict__ w1t)
{
    const int i = blockIdx.x * 256 + threadIdx.x;
    if (i >= XT_GROUPS + WT_GROUPS) return;
    const float* src;
    __nv_bfloat16* dst;
    if (i < XT_GROUPS) {
        src = X + (size_t)i * 8;
        dst = g_xb + (size_t)i * 8;
    } else {
        const int j = i - XT_GROUPS;
        const int n = (j * 8) / DD;
        const int col = (j * 8) % DD;
        const int br = n >> 7, nl = n & 127;
        const float* w = (br == 0) ? w1e : (br == 1) ? w1h : w1t;
        src = w + (size_t)nl * DD + col;
        dst = g_wb + (size_t)n * DD + col;
    }
    float4 a = *(const float4*)src;
    float4 b = *(const float4*)(src + 4);
    __nv_bfloat162 p0 = __floats2bfloat162_rn(a.x, a.y);
    __nv_bfloat162 p1 = __floats2bfloat162_rn(a.z, a.w);
    __nv_bfloat162 p2 = __floats2bfloat162_rn(b.x, b.y);
    __nv_bfloat162 p3 = __floats2bfloat162_rn(b.z, b.w);
    uint4 r;
    r.x = *(uint32_t*)&p0; r.y = *(uint32_t*)&p1;
    r.z = *(uint32_t*)&p2; r.w = *(uint32_t*)&p3;
    *(uint4*)dst = r;
}

// =============================================================
// Kernel 1: h = X @ W1^T + b1 via mma.sync bf16 (HMMA).
// CTA tile 64m x 64n, 4 warps (2x2), warp tile 32x32.
// =============================================================
__global__ __launch_bounds__(128) void k1_mma(
    const float* __restrict__ b1e, const float* __restrict__ b1h,
    const float* __restrict__ b1t)
{
    __shared__ __align__(128) uint8_t sA[64 * 128];
    __shared__ __align__(128) uint8_t sB[64 * 128];

    const int tid  = threadIdx.x;
    const int lane = tid & 31;
    const int wid  = tid >> 5;
    const int nt = blockIdx.x;
    const int mt = blockIdx.y;
    const int m0 = mt * 64;
    const int nbr = nt >> 1;
    const int nl0 = (nt & 1) * 64;
    const int mw = (wid >> 1) * 32;
    const int nw = (wid & 1) * 32;
    const uint32_t sa = smem_u32(sA);
    const uint32_t sb = smem_u32(sB);

    const int lrow = tid >> 3;
    const int lch  = tid & 7;

    float acc[2][4][4] = {};

    uint4 ar[4], br[4];
    {
        const __nv_bfloat16* ag = g_xb + (size_t)(m0 + lrow) * DD + lch * 8;
        const __nv_bfloat16* bg = g_wb + (size_t)(nt * 64 + lrow) * DD + lch * 8;
        #pragma unroll
        for (int i = 0; i < 4; i++) {
            ar[i] = *(const uint4*)(ag + (size_t)i * 16 * DD);
            br[i] = *(const uint4*)(bg + (size_t)i * 16 * DD);
        }
    }

    for (int c = 0; c < 12; c++) {
        __syncthreads();
        #pragma unroll
        for (int i = 0; i < 4; i++) {
            const uint32_t bo = sw128((lrow + i * 16) * 128 + lch * 16);
            *(uint4*)(sA + bo) = ar[i];
            *(uint4*)(sB + bo) = br[i];
        }
        __syncthreads();
        if (c < 11) {
            const int cc = c + 1;
            const __nv_bfloat16* ag = g_xb + (size_t)(m0 + lrow) * DD + cc * 64 + lch * 8;
            const __nv_bfloat16* bg = g_wb + (size_t)(nt * 64 + lrow) * DD + cc * 64 + lch * 8;
            #pragma unroll
            for (int i = 0; i < 4; i++) {
                ar[i] = *(const uint4*)(ag + (size_t)i * 16 * DD);
                br[i] = *(const uint4*)(bg + (size_t)i * 16 * DD);
            }
        }
        #pragma unroll
        for (int ks = 0; ks < 4; ks++) {
            const int kb = ks * 32;
            uint32_t afr[2][4];
            #pragma unroll
            for (int f = 0; f < 2; f++) {
                const int row = mw + f * 16 + (lane & 15);
                const uint32_t addr = sa + sw128(row * 128 + kb + ((lane >> 4) << 4));
                ldmx4(afr[f], addr);
            }
            uint32_t bfr[4][2];
            #pragma unroll
            for (int g2 = 0; g2 < 2; g2++) {
                const int sel = lane >> 3;
                const int row = nw + g2 * 16 + ((sel & 2) ? 8 : 0) + (lane & 7);
                const uint32_t addr = sb + sw128(row * 128 + kb + ((sel & 1) << 4));
                uint32_t t[4];
                ldmx4(t, addr);
                bfr[g2 * 2 + 0][0] = t[0]; bfr[g2 * 2 + 0][1] = t[1];
                bfr[g2 * 2 + 1][0] = t[2]; bfr[g2 * 2 + 1][1] = t[3];
            }
            #pragma unroll
            for (int f = 0; f < 2; f++)
                #pragma unroll
                for (int g = 0; g < 4; g++)
                    mma_bf16(acc[f][g], afr[f], bfr[g]);
        }
    }

    const float* b1 = (nbr == 0) ? b1e : (nbr == 1) ? b1h : b1t;
    #pragma unroll
    for (int f = 0; f < 2; f++) {
        const int mrow = m0 + mw + f * 16 + (lane >> 2);
        #pragma unroll
        for (int g = 0; g < 4; g++) {
            const int nloc = nw + g * 8 + (lane & 3) * 2;
            const float bx = b1[nl0 + nloc], by = b1[nl0 + nloc + 1];
            float2 v0 = { acc[f][g][0] + bx, acc[f][g][1] + by };
            float2 v1 = { acc[f][g][2] + bx, acc[f][g][3] + by };
            *(float2*)&g_h[(size_t)mrow * HDIM + nt * 64 + nloc] = v0;
            *(float2*)&g_h[(size_t)(mrow + 8) * HDIM + nt * 64 + nloc] = v1;
        }
    }
}

// =============================================================
// Kernel 2: per-token prep (q/k deinterleave + RoPE -> bf16,
// bias GEMV)
// =============================================================
#define TPB2 8
__global__ __launch_bounds__(128) void k2_prep(
    const float* __restrict__ w2e, const float* __restrict__ b2e,
    const float* __restrict__ w2h, const float* __restrict__ b2h,
    const float* __restrict__ w2t, const float* __restrict__ b2t)
{
    __shared__ float hrow[TPB2][HDIM];
    __shared__ float w2s[52][129];
    __shared__ float b2s[52];

    const int t0  = blockIdx.x * TPB2;
    const int tid = threadIdx.x;

    for (int f = tid; f < 52*128; f += 128) {
        const int r = f >> 7, e = f & 127;
        const float* src = (r < 4)  ? (w2e + r*128)
                         : (r < 28) ? (w2h + (r-4)*128)
                                    : (w2t + (r-28)*128);
        w2s[r][e] = src[e];
    }
    if (tid < 52)
        b2s[tid] = (tid < 4) ? b2e[tid] : (tid < 28) ? b2h[tid-4] : b2t[tid-28];

    for (int f = tid; f < TPB2*HDIM; f += 128)
        ((float*)hrow)[f] = g_h[(size_t)t0*HDIM + f];
    __syncthreads();

    for (int tt = 0; tt < TPB2; tt++) {
        const int tok = t0 + tt;
        const int b = tok >> 9, n = tok & 511;

        for (int idx = tid; idx < 192; idx += 128) {
            const int ty = idx >> 6, e = idx & 63;
            float qv = hrow[tt][ty*128 + 2*e];
            float kv = hrow[tt][ty*128 + 2*e + 1];
            if (ty == 0) {
                const int i = e >> 1;
                const float inv = powf(10000.0f, -(float)i / 32.0f);
                const float ang = (float)n * inv;
                const float c = cosf(ang), s = sinf(ang);
                const int pe = (e & 1) ? (e - 1) : (e + 1);
                const float qp = hrow[tt][2*pe];
                const float kp = hrow[tt][2*pe + 1];
                const float sgn = (e & 1) ? 1.0f : -1.0f;
                qv = qv*c + sgn*qp*s;
                kv = kv*c + sgn*kp*s;
            }
            g_q[ty][b][n][e] = __float2bfloat16(qv * 0.125f);
            g_k[ty][b][n][e] = __float2bfloat16(kv);
        }

        if (tid < 52) {
            const int base = (tid < 4) ? 0 : (tid < 28) ? 128 : 256;
            const float* hb = &hrow[tt][base];
            float acc = 0.0f;
            #pragma unroll 16
            for (int e = 0; e < 128; e++)
                acc += hb[e] * w2s[tid][e];
            const int ty = (tid < 4) ? 0 : (tid < 28) ? 1 : 2;
            const int j  = (tid < 4) ? tid : (tid < 28) ? tid-4 : tid-28;
            g_bias[ty][b][j][n] = (acc + b2s[tid]) * 0.5f;
        }
    }
}

// =============================================================
// Kernel 3: per (b, 64x64 tile): QK^T via bf16 mma once per type,
// mask folded once, fan out 26 head planes with streaming stores.
// 128 threads: 4 warps compute, all 128 store.
// =============================================================
__global__ __launch_bounds__(128) void k3_out(
    const int* __restrict__ mask, float* __restrict__ out)
{
    __shared__ __align__(128) uint8_t sq[64 * 128];   // 64 rows x 64 bf16, SW128
    __shared__ __align__(128) uint8_t sk[64 * 128];
    __shared__ float sf[64][68];
    __shared__ float bse[12][68];
    __shared__ float bso[12][68];
    __shared__ int   mms[64];
    __shared__ int   mns[64];

    const int n0 = blockIdx.x * 64;
    const int m0 = blockIdx.y * 64;
    const int b  = blockIdx.z;
    const int tid  = threadIdx.x;
    const int lane = tid & 31;
    const int wid  = tid >> 5;
    const int mw = (wid >> 1) * 32;
    const int nw = (wid & 1) * 32;
    const uint32_t sqa = smem_u32(sq);
    const uint32_t ska = smem_u32(sk);

    const int lrow = tid >> 3;    // 0..15 (+16 per i)
    const int lch  = tid & 7;

    if (tid < 64)       mms[tid]      = mask[b*NN + m0 + tid];
    else if (tid < 128) mns[tid - 64] = mask[b*NN + n0 + tid - 64];

    const size_t ENT_SZ = (size_t)BB * 2 * NN * NN;

    // epilogue thread mapping: 8x4 block per thread
    const int ty = tid >> 4;           // 0..7 -> rows ty*8..ty*8+7
    const int tx = tid & 15;           // cols tx*4..tx*4+3

    for (int t = 0; t < 3; t++) {
        const int H = (t == 0) ? 2 : 12;
        __syncthreads();
        // stage q/k tiles (bf16, SW128 swizzle)
        #pragma unroll
        for (int i = 0; i < 4; i++) {
            const int row = lrow + i * 16;
            const uint32_t bo = sw128(row * 128 + lch * 16);
            *(uint4*)(sq + bo) = *(const uint4*)&g_q[t][b][m0 + row][lch * 8];
            *(uint4*)(sk + bo) = *(const uint4*)&g_k[t][b][n0 + row][lch * 8];
        }
        for (int f = tid; f < H * 64; f += 128) {
            const int hd = f >> 6, e = f & 63;
            bse[hd][e] = g_bias[t][b][2*hd][n0 + e];
            bso[hd][e] = g_bias[t][b][2*hd + 1][m0 + e];
        }
        __syncthreads();

        // QK^T: K=64 = 4 k16 steps
        float acc[2][4][4] = {};
        #pragma unroll
        for (int ks = 0; ks < 4; ks++) {
            const int kb = ks * 32;
            uint32_t afr[2][4];
            #pragma unroll
            for (int f = 0; f < 2; f++) {
                const int row = mw + f * 16 + (lane & 15);
                const uint32_t addr = sqa + sw128(row * 128 + kb + ((lane >> 4) << 4));
                ldmx4(afr[f], addr);
            }
            uint32_t bfr[4][2];
            #pragma unroll
            for (int g2 = 0; g2 < 2; g2++) {
                const int sel = lane >> 3;
                const int row = nw + g2 * 16 + ((sel & 2) ? 8 : 0) + (lane & 7);
                const uint32_t addr = ska + sw128(row * 128 + kb + ((sel & 1) << 4));
                uint32_t tr[4];
                ldmx4(tr, addr);
                bfr[g2 * 2 + 0][0] = tr[0]; bfr[g2 * 2 + 0][1] = tr[1];
                bfr[g2 * 2 + 1][0] = tr[2]; bfr[g2 * 2 + 1][1] = tr[3];
            }
            #pragma unroll
            for (int f = 0; f < 2; f++)
                #pragma unroll
                for (int g = 0; g < 4; g++)
                    mma_bf16(acc[f][g], afr[f], bfr[g]);
        }

        // fragments -> sf (row-major)
        #pragma unroll
        for (int f = 0; f < 2; f++) {
            const int r = mw + f * 16 + (lane >> 2);
            #pragma unroll
            for (int g = 0; g < 4; g++) {
                const int c = nw + g * 8 + (lane & 3) * 2;
                sf[r][c]     = acc[f][g][0];
                sf[r][c + 1] = acc[f][g][1];
                sf[r + 8][c]     = acc[f][g][2];
                sf[r + 8][c + 1] = acc[f][g][3];
            }
        }
        __syncthreads();

        // fold masks once per type
        int nj[4];
        #pragma unroll
        for (int j = 0; j < 4; j++) nj[j] = mns[tx*4 + j];

        float accm[8][4];
        #pragma unroll
        for (int i = 0; i < 8; i++) {
            const int r = ty*8 + i;
            const int mi = mms[r];
            float4 v = *(const float4*)&sf[r][tx*4];
            float* vv = &v.x;
            #pragma unroll
            for (int j = 0; j < 4; j++) {
                float sub = 0.0f;
                if (!(mi & nj[j])) sub = NEGF;
                if (t == 0 && (m0 + r) > (n0 + tx*4 + j)) sub += NEGF;
                accm[i][j] = vv[j] - sub;
            }
        }

        const size_t base = (t == 0) ? 0
                          : (t == 1) ? ENT_SZ
                                     : ENT_SZ + (size_t)BB*12*NN*NN;

        for (int hd = 0; hd < H; hd++) {
            float4 bev = *(const float4*)&bse[hd][tx*4];
            const float beo[4] = {bev.x, bev.y, bev.z, bev.w};
            float* op = out + base
                      + (((size_t)(b*H + hd)) * NN + (m0 + ty*8)) * NN
                      + n0 + tx*4;
            #pragma unroll
            for (int i = 0; i < 8; i++) {
                const float bo = bso[hd][ty*8 + i];
                float4 o;
                o.x = accm[i][0] + beo[0] + bo;
                o.y = accm[i][1] + beo[1] + bo;
                o.z = accm[i][2] + beo[2] + bo;
                o.w = accm[i][3] + beo[3] + bo;
                __stcs((float4*)(op + (size_t)i * NN), o);
            }
        }
    }
}

// =============================================================
extern "C" void kernel_launch(void* const* d_in, const int* in_sizes, int n_in,
                              void* d_out, int out_size)
{
    (void)in_sizes; (void)n_in; (void)out_size;
    const float* chars = (const float*)d_in[0];
    const int*   mask  = (const int*)  d_in[1];
    const float* w1e = (const float*)d_in[2];
    const float* b1e = (const float*)d_in[3];
    const float* w2e = (const float*)d_in[4];
    const float* b2e = (const float*)d_in[5];
    const float* w1h = (const float*)d_in[6];
    const float* b1h = (const float*)d_in[7];
    const float* w2h = (const float*)d_in[8];
    const float* b2h = (const float*)d_in[9];
    const float* w1t = (const float*)d_in[10];
    const float* b1t = (const float*)d_in[11];
    const float* w2t = (const float*)d_in[12];
    const float* b2t = (const float*)d_in[13];
    float* out = (float*)d_out;

    const int cvt_groups = XT_GROUPS + WT_GROUPS;
    k0_convert<<<(cvt_groups + 255) / 256, 256>>>(chars, w1e, w1h, w1t);

    dim3 g1(6, 64);
    k1_mma<<<g1, 128>>>(b1e, b1h, b1t);

    k2_prep<<<TOK / TPB2, 128>>>(w2e, b2e, w2h, b2h, w2t, b2t);

    dim3 g3(8, 8, 8);
    k3_out<<<g3, 128>>>(mask, out);
}

// round 9
// speedup vs baseline: 2.3196x; 1.0004x over previous
#include <cuda_runtime.h>
#include <cuda_bf16.h>
#include <cstdint>

#define BB 8
#define NN 512
#define DD 768
#define HSZ 64
#define TOK (BB*NN)        // 4096
#define HDIM 384           // 3 * 128
#define NEGF 1e12f

// ---------------- scratch (no allocs allowed) ----------------
__device__ float g_h[TOK*HDIM];                   // h rows for 3 types
__device__ __nv_bfloat16 g_xb[TOK*DD];            // chars in bf16
__device__ __nv_bfloat16 g_wb[HDIM*DD];           // w1 (ent|head|tail) in bf16
__device__ __nv_bfloat16 g_q[3][BB][NN][HSZ];     // bf16 q (scaled 1/8, rope'd)
__device__ __nv_bfloat16 g_k[3][BB][NN][HSZ];     // bf16 k
__device__ float g_bias[3][BB][24][NN];

__device__ __forceinline__ uint32_t smem_u32(const void* p) {
    uint32_t a;
    asm("{ .reg .u64 t; cvta.to.shared.u64 t, %1; cvt.u32.u64 %0, t; }" : "=r"(a) : "l"(p));
    return a;
}
__device__ __forceinline__ uint32_t sw128(uint32_t off) {
    return off ^ ((off >> 3) & 0x70);
}
__device__ __forceinline__ void ldmx4(uint32_t* r, uint32_t addr) {
    asm volatile("ldmatrix.sync.aligned.m8n8.x4.shared.b16 {%0,%1,%2,%3}, [%4];"
                 : "=r"(r[0]), "=r"(r[1]), "=r"(r[2]), "=r"(r[3]) : "r"(addr));
}
__device__ __forceinline__ void mma_bf16(float* d, const uint32_t* a, const uint32_t* b) {
    asm volatile(
        "mma.sync.aligned.m16n8k16.row.col.f32.bf16.bf16.f32 "
        "{%0,%1,%2,%3}, {%4,%5,%6,%7}, {%8,%9}, {%0,%1,%2,%3};"
        : "+f"(d[0]), "+f"(d[1]), "+f"(d[2]), "+f"(d[3])
        : "r"(a[0]), "r"(a[1]), "r"(a[2]), "r"(a[3]), "r"(b[0]), "r"(b[1]));
}

// =============================================================
// Kernel 0: fp32 -> bf16 convert for X and W1(ent|head|tail)
// =============================================================
#define XT_GROUPS (TOK*DD/8)      // 393216
#define WT_GROUPS (HDIM*DD/8)     // 36864
__global__ __launch_bounds__(256) void k0_convert(
    const float* __restrict__ X,
    const float* __restrict__ w1e, const float* __restrict__ w1h,
    const float* __restrict__ w1t)
{
    const int i = blockIdx.x * 256 + threadIdx.x;
    if (i >= XT_GROUPS + WT_GROUPS) return;
    const float* src;
    __nv_bfloat16* dst;
    if (i < XT_GROUPS) {
        src = X + (size_t)i * 8;
        dst = g_xb + (size_t)i * 8;
    } else {
        const int j = i - XT_GROUPS;
        const int n = (j * 8) / DD;
        const int col = (j * 8) % DD;
        const int br = n >> 7, nl = n & 127;
        const float* w = (br == 0) ? w1e : (br == 1) ? w1h : w1t;
        src = w + (size_t)nl * DD + col;
        dst = g_wb + (size_t)n * DD + col;
    }
    float4 a = *(const float4*)src;
    float4 b = *(const float4*)(src + 4);
    __nv_bfloat162 p0 = __floats2bfloat162_rn(a.x, a.y);
    __nv_bfloat162 p1 = __floats2bfloat162_rn(a.z, a.w);
    __nv_bfloat162 p2 = __floats2bfloat162_rn(b.x, b.y);
    __nv_bfloat162 p3 = __floats2bfloat162_rn(b.z, b.w);
    uint4 r;
    r.x = *(uint32_t*)&p0; r.y = *(uint32_t*)&p1;
    r.z = *(uint32_t*)&p2; r.w = *(uint32_t*)&p3;
    *(uint4*)dst = r;
}

// =============================================================
// Kernel 1: h = X @ W1^T + b1 via mma.sync bf16 (HMMA).
// CTA tile 64m x 64n, 4 warps (2x2), warp tile 32x32.
// =============================================================
__global__ __launch_bounds__(128) void k1_mma(
    const float* __restrict__ b1e, const float* __restrict__ b1h,
    const float* __restrict__ b1t)
{
    __shared__ __align__(128) uint8_t sA[64 * 128];
    __shared__ __align__(128) uint8_t sB[64 * 128];

    const int tid  = threadIdx.x;
    const int lane = tid & 31;
    const int wid  = tid >> 5;
    const int nt = blockIdx.x;
    const int mt = blockIdx.y;
    const int m0 = mt * 64;
    const int nbr = nt >> 1;
    const int nl0 = (nt & 1) * 64;
    const int mw = (wid >> 1) * 32;
    const int nw = (wid & 1) * 32;
    const uint32_t sa = smem_u32(sA);
    const uint32_t sb = smem_u32(sB);

    const int lrow = tid >> 3;
    const int lch  = tid & 7;

    float acc[2][4][4] = {};

    uint4 ar[4], br[4];
    {
        const __nv_bfloat16* ag = g_xb + (size_t)(m0 + lrow) * DD + lch * 8;
        const __nv_bfloat16* bg = g_wb + (size_t)(nt * 64 + lrow) * DD + lch * 8;
        #pragma unroll
        for (int i = 0; i < 4; i++) {
            ar[i] = *(const uint4*)(ag + (size_t)i * 16 * DD);
            br[i] = *(const uint4*)(bg + (size_t)i * 16 * DD);
        }
    }

    for (int c = 0; c < 12; c++) {
        __syncthreads();
        #pragma unroll
        for (int i = 0; i < 4; i++) {
            const uint32_t bo = sw128((lrow + i * 16) * 128 + lch * 16);
            *(uint4*)(sA + bo) = ar[i];
            *(uint4*)(sB + bo) = br[i];
        }
        __syncthreads();
        if (c < 11) {
            const int cc = c + 1;
            const __nv_bfloat16* ag = g_xb + (size_t)(m0 + lrow) * DD + cc * 64 + lch * 8;
            const __nv_bfloat16* bg = g_wb + (size_t)(nt * 64 + lrow) * DD + cc * 64 + lch * 8;
            #pragma unroll
            for (int i = 0; i < 4; i++) {
                ar[i] = *(const uint4*)(ag + (size_t)i * 16 * DD);
                br[i] = *(const uint4*)(bg + (size_t)i * 16 * DD);
            }
        }
        #pragma unroll
        for (int ks = 0; ks < 4; ks++) {
            const int kb = ks * 32;
            uint32_t afr[2][4];
            #pragma unroll
            for (int f = 0; f < 2; f++) {
                const int row = mw + f * 16 + (lane & 15);
                const uint32_t addr = sa + sw128(row * 128 + kb + ((lane >> 4) << 4));
                ldmx4(afr[f], addr);
            }
            uint32_t bfr[4][2];
            #pragma unroll
            for (int g2 = 0; g2 < 2; g2++) {
                const int sel = lane >> 3;
                const int row = nw + g2 * 16 + ((sel & 2) ? 8 : 0) + (lane & 7);
                const uint32_t addr = sb + sw128(row * 128 + kb + ((sel & 1) << 4));
                uint32_t t[4];
                ldmx4(t, addr);
                bfr[g2 * 2 + 0][0] = t[0]; bfr[g2 * 2 + 0][1] = t[1];
                bfr[g2 * 2 + 1][0] = t[2]; bfr[g2 * 2 + 1][1] = t[3];
            }
            #pragma unroll
            for (int f = 0; f < 2; f++)
                #pragma unroll
                for (int g = 0; g < 4; g++)
                    mma_bf16(acc[f][g], afr[f], bfr[g]);
        }
    }

    const float* b1 = (nbr == 0) ? b1e : (nbr == 1) ? b1h : b1t;
    #pragma unroll
    for (int f = 0; f < 2; f++) {
        const int mrow = m0 + mw + f * 16 + (lane >> 2);
        #pragma unroll
        for (int g = 0; g < 4; g++) {
            const int nloc = nw + g * 8 + (lane & 3) * 2;
            const float bx = b1[nl0 + nloc], by = b1[nl0 + nloc + 1];
            float2 v0 = { acc[f][g][0] + bx, acc[f][g][1] + by };
            float2 v1 = { acc[f][g][2] + bx, acc[f][g][3] + by };
            *(float2*)&g_h[(size_t)mrow * HDIM + nt * 64 + nloc] = v0;
            *(float2*)&g_h[(size_t)(mrow + 8) * HDIM + nt * 64 + nloc] = v1;
        }
    }
}

// =============================================================
// Kernel 2: per-token prep (q/k deinterleave + RoPE -> bf16,
// bias GEMV with split-K + multi-accumulator)
// =============================================================
#define TPB2 8
__global__ __launch_bounds__(128) void k2_prep(
    const float* __restrict__ w2e, const float* __restrict__ b2e,
    const float* __restrict__ w2h, const float* __restrict__ b2h,
    const float* __restrict__ w2t, const float* __restrict__ b2t)
{
    __shared__ float hrow[TPB2][HDIM];
    __shared__ float w2s[52][129];
    __shared__ float b2s[52];
    __shared__ float invs[32];
    __shared__ float part[52];

    const int t0  = blockIdx.x * TPB2;
    const int tid = threadIdx.x;

    for (int f = tid; f < 52*128; f += 128) {
        const int r = f >> 7, e = f & 127;
        const float* src = (r < 4)  ? (w2e + r*128)
                         : (r < 28) ? (w2h + (r-4)*128)
                                    : (w2t + (r-28)*128);
        w2s[r][e] = src[e];
    }
    if (tid < 52)
        b2s[tid] = (tid < 4) ? b2e[tid] : (tid < 28) ? b2h[tid-4] : b2t[tid-28];
    if (tid < 32)
        invs[tid] = exp2f(-(float)tid * 0.4152410118609203f);  // 10000^(-i/32)

    for (int f = tid; f < TPB2*HDIM; f += 128)
        ((float*)hrow)[f] = g_h[(size_t)t0*HDIM + f];
    __syncthreads();

    for (int tt = 0; tt < TPB2; tt++) {
        const int tok = t0 + tt;
        const int b = tok >> 9, n = tok & 511;

        for (int idx = tid; idx < 192; idx += 128) {
            const int ty = idx >> 6, e = idx & 63;
            float qv = hrow[tt][ty*128 + 2*e];
            float kv = hrow[tt][ty*128 + 2*e + 1];
            if (ty == 0) {
                const int i = e >> 1;
                const float ang = (float)n * invs[i];
                float s, c;
                sincosf(ang, &s, &c);
                const int pe = (e & 1) ? (e - 1) : (e + 1);
                const float qp = hrow[tt][2*pe];
                const float kp = hrow[tt][2*pe + 1];
                const float sgn = (e & 1) ? 1.0f : -1.0f;
                qv = qv*c + sgn*qp*s;
                kv = kv*c + sgn*kp*s;
            }
            g_q[ty][b][n][e] = __float2bfloat16(qv * 0.125f);
            g_k[ty][b][n][e] = __float2bfloat16(kv);
        }

        // bias GEMV: 52 outputs, split K=128 over 2 threads, 4 accumulators
        float s = 0.0f;
        if (tid < 104) {
            const int j  = (tid < 52) ? tid : tid - 52;
            const int hf = (tid < 52) ? 0 : 1;
            const int base = (j < 4) ? 0 : (j < 28) ? 128 : 256;
            const float* hb = &hrow[tt][base + hf*64];
            const float* wr = &w2s[j][hf*64];
            float a0 = 0, a1 = 0, a2 = 0, a3 = 0;
            #pragma unroll
            for (int e = 0; e < 64; e += 4) {
                a0 += hb[e]   * wr[e];
                a1 += hb[e+1] * wr[e+1];
                a2 += hb[e+2] * wr[e+2];
                a3 += hb[e+3] * wr[e+3];
            }
            s = (a0 + a1) + (a2 + a3);
        }
        if (tid >= 52 && tid < 104) part[tid - 52] = s;
        __syncthreads();
        if (tid < 52) {
            const float total = s + part[tid];
            const int ty = (tid < 4) ? 0 : (tid < 28) ? 1 : 2;
            const int j  = (tid < 4) ? tid : (tid < 28) ? tid-4 : tid-28;
            g_bias[ty][b][j][n] = (total + b2s[tid]) * 0.5f;
        }
        __syncthreads();
    }
}

// =============================================================
// Kernel 3: per (b, 64x64 tile): QK^T via bf16 mma once per type,
// mask folded once, fan out 26 head planes with streaming stores.
// 256 threads / 8 warps (warp tile 16x32); sf unions with staging.
// =============================================================
__global__ __launch_bounds__(256, 3) void k3_out(
    const int* __restrict__ mask, float* __restrict__ out)
{
    __shared__ __align__(128) uint8_t buf[64 * 68 * 4];  // sq|sk staging, then sf
    __shared__ float bse[12][68];
    __shared__ float bso[12][68];
    __shared__ int   mms[64];
    __shared__ int   mns[64];

    uint8_t* sq = buf;               // 64 x 128B
    uint8_t* sk = buf + 8192;        // 64 x 128B
    float (*sf)[68] = (float(*)[68])buf;

    const int n0 = blockIdx.x * 64;
    const int m0 = blockIdx.y * 64;
    const int b  = blockIdx.z;
    const int tid  = threadIdx.x;
    const int lane = tid & 31;
    const int wid  = tid >> 5;
    const int mw = (wid >> 1) * 16;        // 4 row groups of 16
    const int nw = (wid & 1) * 32;         // 2 col groups of 32
    const uint32_t sqa = smem_u32(sq);
    const uint32_t ska = smem_u32(sk);

    if (tid < 64)       mms[tid]      = mask[b*NN + m0 + tid];
    else if (tid < 128) mns[tid - 64] = mask[b*NN + n0 + tid - 64];

    const size_t ENT_SZ = (size_t)BB * 2 * NN * NN;

    // epilogue mapping: 4x4 block per thread
    const int ty = tid >> 4;           // 0..15 -> rows ty*4..ty*4+3
    const int tx = tid & 15;           // cols tx*4..tx*4+3

    for (int t = 0; t < 3; t++) {
        const int H = (t == 0) ? 2 : 12;
        __syncthreads();   // protect buf reuse (prev sf reads done) + masks on t=0
        // stage q/k tiles (bf16, SW128 swizzle): 2 uint4 per tile per thread
        #pragma unroll
        for (int i = 0; i < 2; i++) {
            const int lin = i * 256 + tid;
            const int row = lin >> 3, ch = lin & 7;
            const uint32_t bo = sw128(row * 128 + ch * 16);
            *(uint4*)(sq + bo) = *(const uint4*)&g_q[t][b][m0 + row][ch * 8];
            *(uint4*)(sk + bo) = *(const uint4*)&g_k[t][b][n0 + row][ch * 8];
        }
        for (int f = tid; f < H * 64; f += 256) {
            const int hd = f >> 6, e = f & 63;
            bse[hd][e] = g_bias[t][b][2*hd][n0 + e];
            bso[hd][e] = g_bias[t][b][2*hd + 1][m0 + e];
        }
        __syncthreads();

        // QK^T: warp tile 16x32, K=64 = 4 k16 steps
        float acc[4][4] = {};
        #pragma unroll
        for (int ks = 0; ks < 4; ks++) {
            const int kb = ks * 32;
            uint32_t afr[4];
            {
                const int row = mw + (lane & 15);
                const uint32_t addr = sqa + sw128(row * 128 + kb + ((lane >> 4) << 4));
                ldmx4(afr, addr);
            }
            uint32_t bfr[4][2];
            #pragma unroll
            for (int g2 = 0; g2 < 2; g2++) {
                const int sel = lane >> 3;
                const int row = nw + g2 * 16 + ((sel & 2) ? 8 : 0) + (lane & 7);
                const uint32_t addr = ska + sw128(row * 128 + kb + ((sel & 1) << 4));
                uint32_t tr[4];
                ldmx4(tr, addr);
                bfr[g2 * 2 + 0][0] = tr[0]; bfr[g2 * 2 + 0][1] = tr[1];
                bfr[g2 * 2 + 1][0] = tr[2]; bfr[g2 * 2 + 1][1] = tr[3];
            }
            #pragma unroll
            for (int g = 0; g < 4; g++)
                mma_bf16(acc[g], afr, bfr[g]);
        }
        __syncthreads();   // all warps done reading sq/sk before sf overwrite

        // fragments -> sf (row-major), overlaying staging buffer
        {
            const int r = mw + (lane >> 2);
            #pragma unroll
            for (int g = 0; g < 4; g++) {
                const int c = nw + g * 8 + (lane & 3) * 2;
                sf[r][c]     = acc[g][0];
                sf[r][c + 1] = acc[g][1];
                sf[r + 8][c]     = acc[g][2];
                sf[r + 8][c + 1] = acc[g][3];
            }
        }
        __syncthreads();

        // fold masks once per type
        int nj[4];
        #pragma unroll
        for (int j = 0; j < 4; j++) nj[j] = mns[tx*4 + j];

        float accm[4][4];
        #pragma unroll
        for (int i = 0; i < 4; i++) {
            const int r = ty*4 + i;
            const int mi = mms[r];
            float4 v = *(const float4*)&sf[r][tx*4];
            float* vv = &v.x;
            #pragma unroll
            for (int j = 0; j < 4; j++) {
                float sub = 0.0f;
                if (!(mi & nj[j])) sub = NEGF;
                if (t == 0 && (m0 + r) > (n0 + tx*4 + j)) sub += NEGF;
                accm[i][j] = vv[j] - sub;
            }
        }

        const size_t base = (t == 0) ? 0
                          : (t == 1) ? ENT_SZ
                                     : ENT_SZ + (size_t)BB*12*NN*NN;

        for (int hd = 0; hd < H; hd++) {
            float4 bev = *(const float4*)&bse[hd][tx*4];
            const float beo[4] = {bev.x, bev.y, bev.z, bev.w};
            float* op = out + base
                      + (((size_t)(b*H + hd)) * NN + (m0 + ty*4)) * NN
                      + n0 + tx*4;
            #pragma unroll
            for (int i = 0; i < 4; i++) {
                const float bo = bso[hd][ty*4 + i];
                float4 o;
                o.x = accm[i][0] + beo[0] + bo;
                o.y = accm[i][1] + beo[1] + bo;
                o.z = accm[i][2] + beo[2] + bo;
                o.w = accm[i][3] + beo[3] + bo;
                __stcs((float4*)(op + (size_t)i * NN), o);
            }
        }
    }
}

// =============================================================
extern "C" void kernel_launch(void* const* d_in, const int* in_sizes, int n_in,
                              void* d_out, int out_size)
{
    (void)in_sizes; (void)n_in; (void)out_size;
    const float* chars = (const float*)d_in[0];
    const int*   mask  = (const int*)  d_in[1];
    const float* w1e = (const float*)d_in[2];
    const float* b1e = (const float*)d_in[3];
    const float* w2e = (const float*)d_in[4];
    const float* b2e = (const float*)d_in[5];
    const float* w1h = (const float*)d_in[6];
    const float* b1h = (const float*)d_in[7];
    const float* w2h = (const float*)d_in[8];
    const float* b2h = (const float*)d_in[9];
    const float* w1t = (const float*)d_in[10];
    const float* b1t = (const float*)d_in[11];
    const float* w2t = (const float*)d_in[12];
    const float* b2t = (const float*)d_in[13];
    float* out = (float*)d_out;

    const int cvt_groups = XT_GROUPS + WT_GROUPS;
    k0_convert<<<(cvt_groups + 255) / 256, 256>>>(chars, w1e, w1h, w1t);

    dim3 g1(6, 64);
    k1_mma<<<g1, 128>>>(b1e, b1h, b1t);

    k2_prep<<<TOK / TPB2, 128>>>(w2e, b2e, w2h, b2h, w2t, b2t);

    dim3 g3(8, 8, 8);
    k3_out<<<g3, 256>>>(mask, out);
}

// round 15
// speedup vs baseline: 2.5294x; 1.0905x over previous
#include <cuda_runtime.h>
#include <cuda_bf16.h>
#include <cstdint>

#define BB 8
#define NN 512
#define DD 768
#define HSZ 64
#define TOK (BB*NN)        // 4096
#define HDIM 384           // 3 * 128
#define NEGF 1e12f

// ---------------- scratch (no allocs allowed) ----------------
__device__ __nv_bfloat16 g_xb[TOK*DD];            // chars in bf16
__device__ __nv_bfloat16 g_wb[HDIM*DD];           // w1 (ent|head|tail) in bf16
__device__ __nv_bfloat16 g_q[3][BB][NN][HSZ];     // bf16 q (scaled 1/8, rope'd)
__device__ __nv_bfloat16 g_k[3][BB][NN][HSZ];     // bf16 k
__device__ float g_bias[3][BB][24][NN];

__device__ __forceinline__ uint32_t smem_u32(const void* p) {
    uint32_t a;
    asm("{ .reg .u64 t; cvta.to.shared.u64 t, %1; cvt.u32.u64 %0, t; }" : "=r"(a) : "l"(p));
    return a;
}
__device__ __forceinline__ uint32_t sw128(uint32_t off) {
    return off ^ ((off >> 3) & 0x70);
}
__device__ __forceinline__ void ldmx4(uint32_t* r, uint32_t addr) {
    asm volatile("ldmatrix.sync.aligned.m8n8.x4.shared.b16 {%0,%1,%2,%3}, [%4];"
                 : "=r"(r[0]), "=r"(r[1]), "=r"(r[2]), "=r"(r[3]) : "r"(addr));
}
__device__ __forceinline__ void mma_bf16(float* d, const uint32_t* a, const uint32_t* b) {
    asm volatile(
        "mma.sync.aligned.m16n8k16.row.col.f32.bf16.bf16.f32 "
        "{%0,%1,%2,%3}, {%4,%5,%6,%7}, {%8,%9}, {%0,%1,%2,%3};"
        : "+f"(d[0]), "+f"(d[1]), "+f"(d[2]), "+f"(d[3])
        : "r"(a[0]), "r"(a[1]), "r"(a[2]), "r"(a[3]), "r"(b[0]), "r"(b[1]));
}

// =============================================================
// Kernel 0: fp32 -> bf16 convert for X and W1(ent|head|tail)
// =============================================================
#define XT_GROUPS (TOK*DD/8)      // 393216
#define WT_GROUPS (HDIM*DD/8)     // 36864
__global__ __launch_bounds__(256) void k0_convert(
    const float* __restrict__ X,
    const float* __restrict__ w1e, const float* __restrict__ w1h,
    const float* __restrict__ w1t)
{
    const int i = blockIdx.x * 256 + threadIdx.x;
    if (i >= XT_GROUPS + WT_GROUPS) return;
    const float* src;
    __nv_bfloat16* dst;
    if (i < XT_GROUPS) {
        src = X + (size_t)i * 8;
        dst = g_xb + (size_t)i * 8;
    } else {
        const int j = i - XT_GROUPS;
        const int n = (j * 8) / DD;
        const int col = (j * 8) % DD;
        const int br = n >> 7, nl = n & 127;
        const float* w = (br == 0) ? w1e : (br == 1) ? w1h : w1t;
        src = w + (size_t)nl * DD + col;
        dst = g_wb + (size_t)n * DD + col;
    }
    float4 a = *(const float4*)src;
    float4 b = *(const float4*)(src + 4);
    __nv_bfloat162 p0 = __floats2bfloat162_rn(a.x, a.y);
    __nv_bfloat162 p1 = __floats2bfloat162_rn(a.z, a.w);
    __nv_bfloat162 p2 = __floats2bfloat162_rn(b.x, b.y);
    __nv_bfloat162 p3 = __floats2bfloat162_rn(b.z, b.w);
    uint4 r;
    r.x = *(uint32_t*)&p0; r.y = *(uint32_t*)&p1;
    r.z = *(uint32_t*)&p2; r.w = *(uint32_t*)&p3;
    *(uint4*)dst = r;
}

// =============================================================
// Kernel 12 (fused k1+k2): per (type, 64-row tile):
//   h[64][128] = X @ W1_t^T + b1_t   (HMMA, 8 warps 2x4, 32x32 tiles)
//   -> q/k deinterleave (+RoPE for ent) -> bf16 g_q/g_k
//   -> bias GEMV -> g_bias
// g_h never materialized.
// =============================================================
__global__ __launch_bounds__(256) void k12_fused(
    const float* __restrict__ b1e, const float* __restrict__ b1h,
    const float* __restrict__ b1t,
    const float* __restrict__ w2e, const float* __restrict__ b2e,
    const float* __restrict__ w2h, const float* __restrict__ b2h,
    const float* __restrict__ w2t, const float* __restrict__ b2t)
{
    // buf: GEMM phase = sA (8KB) | sB (16KB); prep phase = sf[64][133] fp32
    __shared__ __align__(128) uint8_t buf[64 * 133 * 4];   // 34048 B
    __shared__ float w2s[24][129];                          // 12384 B
    __shared__ float b1s[128];
    __shared__ float b2s[24];
    __shared__ float invs[32];

    uint8_t* sA = buf;                // 64 rows x 128B
    uint8_t* sB = buf + 8192;         // 128 rows x 128B
    float (*sf)[133] = (float(*)[133])buf;

    const int tid  = threadIdx.x;
    const int lane = tid & 31;
    const int wid  = tid >> 5;
    const int t  = blockIdx.x;        // type 0..2
    const int mt = blockIdx.y;        // 0..63
    const int m0 = mt * 64;
    const int H2 = (t == 0) ? 2 : 12;

    const uint32_t sa = smem_u32(sA);
    const uint32_t sb = smem_u32(sB);

    const int mw = (wid >> 2) * 32;   // 2 row groups
    const int nw = (wid & 3) * 32;    // 4 col groups

    // stage small params
    const float* b1 = (t == 0) ? b1e : (t == 1) ? b1h : b1t;
    const float* w2 = (t == 0) ? w2e : (t == 1) ? w2h : w2t;
    const float* b2 = (t == 0) ? b2e : (t == 1) ? b2h : b2t;
    if (tid < 128) b1s[tid] = b1[tid];
    if (tid < 24 && tid < 2*H2) b2s[tid] = b2[tid];
    if (tid < 32) invs[tid] = exp2f(-(float)tid * 0.4152410118609203f); // 10000^(-i/32)
    for (int f = tid; f < 2*H2*128; f += 256) {
        const int r = f >> 7, e = f & 127;
        w2s[r][e] = w2[r*128 + e];
    }

    // ---------------- GEMM: 64x128, K=768 ----------------
    float acc[2][4][4] = {};
    uint4 ar[2], br[4];
    {
        #pragma unroll
        for (int i = 0; i < 2; i++) {
            const int lin = i * 256 + tid;
            const int row = lin >> 3, ch = lin & 7;
            ar[i] = *(const uint4*)(g_xb + (size_t)(m0 + row) * DD + ch * 8);
        }
        #pragma unroll
        for (int i = 0; i < 4; i++) {
            const int lin = i * 256 + tid;
            const int row = lin >> 3, ch = lin & 7;
            br[i] = *(const uint4*)(g_wb + (size_t)(t * 128 + row) * DD + ch * 8);
        }
    }

    for (int c = 0; c < 12; c++) {
        __syncthreads();
        #pragma unroll
        for (int i = 0; i < 2; i++) {
            const int lin = i * 256 + tid;
            const int row = lin >> 3, ch = lin & 7;
            *(uint4*)(sA + sw128(row * 128 + ch * 16)) = ar[i];
        }
        #pragma unroll
        for (int i = 0; i < 4; i++) {
            const int lin = i * 256 + tid;
            const int row = lin >> 3, ch = lin & 7;
            *(uint4*)(sB + sw128(row * 128 + ch * 16)) = br[i];
        }
        __syncthreads();
        if (c < 11) {
            const int cc = c + 1;
            #pragma unroll
            for (int i = 0; i < 2; i++) {
                const int lin = i * 256 + tid;
                const int row = lin >> 3, ch = lin & 7;
                ar[i] = *(const uint4*)(g_xb + (size_t)(m0 + row) * DD + cc * 64 + ch * 8);
            }
            #pragma unroll
            for (int i = 0; i < 4; i++) {
                const int lin = i * 256 + tid;
                const int row = lin >> 3, ch = lin & 7;
                br[i] = *(const uint4*)(g_wb + (size_t)(t * 128 + row) * DD + cc * 64 + ch * 8);
            }
        }
        #pragma unroll
        for (int ks = 0; ks < 4; ks++) {
            const int kb = ks * 32;
            uint32_t afr[2][4];
            #pragma unroll
            for (int f = 0; f < 2; f++) {
                const int row = mw + f * 16 + (lane & 15);
                ldmx4(afr[f], sa + sw128(row * 128 + kb + ((lane >> 4) << 4)));
            }
            uint32_t bfr[4][2];
            #pragma unroll
            for (int g2 = 0; g2 < 2; g2++) {
                const int sel = lane >> 3;
                const int row = nw + g2 * 16 + ((sel & 2) ? 8 : 0) + (lane & 7);
                uint32_t tr[4];
                ldmx4(tr, sb + sw128(row * 128 + kb + ((sel & 1) << 4)));
                bfr[g2 * 2 + 0][0] = tr[0]; bfr[g2 * 2 + 0][1] = tr[1];
                bfr[g2 * 2 + 1][0] = tr[2]; bfr[g2 * 2 + 1][1] = tr[3];
            }
            #pragma unroll
            for (int f = 0; f < 2; f++)
                #pragma unroll
                for (int g = 0; g < 4; g++)
                    mma_bf16(acc[f][g], afr[f], bfr[g]);
        }
    }
    __syncthreads();   // all warps done reading sA/sB before sf overwrite

    // fragments + b1 -> sf
    #pragma unroll
    for (int f = 0; f < 2; f++) {
        const int r = mw + f * 16 + (lane >> 2);
        #pragma unroll
        for (int g = 0; g < 4; g++) {
            const int cidx = nw + g * 8 + (lane & 3) * 2;
            sf[r][cidx]     = acc[f][g][0] + b1s[cidx];
            sf[r][cidx + 1] = acc[f][g][1] + b1s[cidx + 1];
            sf[r + 8][cidx]     = acc[f][g][2] + b1s[cidx];
            sf[r + 8][cidx + 1] = acc[f][g][3] + b1s[cidx + 1];
        }
    }
    __syncthreads();

    // ---------------- q/k deinterleave (+RoPE) ----------------
    // 64 rows x 32 e-pairs; each item handles elems (2p, 2p+1)
    #pragma unroll
    for (int it = 0; it < 8; it++) {
        const int lin = it * 256 + tid;
        const int r = lin >> 5, p = lin & 31;
        const int tok = m0 + r;
        const int b = tok >> 9, n = tok & 511;
        float q0 = sf[r][4*p],     q1 = sf[r][4*p + 2];
        float k0 = sf[r][4*p + 1], k1 = sf[r][4*p + 3];
        if (t == 0) {
            const float ang = (float)n * invs[p];
            float s, cth;
            sincosf(ang, &s, &cth);
            const float nq0 = q0*cth - q1*s, nq1 = q1*cth + q0*s;
            const float nk0 = k0*cth - k1*s, nk1 = k1*cth + k0*s;
            q0 = nq0; q1 = nq1; k0 = nk0; k1 = nk1;
        }
        __nv_bfloat162 qv = __floats2bfloat162_rn(q0 * 0.125f, q1 * 0.125f);
        __nv_bfloat162 kv = __floats2bfloat162_rn(k0, k1);
        *(__nv_bfloat162*)&g_q[t][b][n][2*p] = qv;
        *(__nv_bfloat162*)&g_k[t][b][n][2*p] = kv;
    }

    // ---------------- bias GEMV ----------------
    // items: j in [0, 2*H2), tok in [0,64): lin = j*64 + tok
    const int nb = (t == 0) ? 1 : 6;
    for (int it = 0; it < nb; it++) {
        const int lin = it * 256 + tid;
        const int j = lin >> 6, r = lin & 63;
        const int tok = m0 + r;
        const int b = tok >> 9, n = tok & 511;
        const float* hb = sf[r];
        const float* wr = w2s[j];
        float a0 = 0, a1 = 0, a2 = 0, a3 = 0;
        #pragma unroll
        for (int e = 0; e < 128; e += 4) {
            a0 += hb[e]   * wr[e];
            a1 += hb[e+1] * wr[e+1];
            a2 += hb[e+2] * wr[e+2];
            a3 += hb[e+3] * wr[e+3];
        }
        g_bias[t][b][j][n] = ((a0 + a1) + (a2 + a3) + b2s[j]) * 0.5f;
    }
}

// =============================================================
// Kernel 3 (R8 config): per (b, 64x64 tile): QK^T via bf16 mma
// once per type, mask folded once, 26-plane fan-out, stcs.
// 128 threads / 4 warps.
// =============================================================
__global__ __launch_bounds__(128) void k3_out(
    const int* __restrict__ mask, float* __restrict__ out)
{
    __shared__ __align__(128) uint8_t sq[64 * 128];
    __shared__ __align__(128) uint8_t sk[64 * 128];
    __shared__ float sf[64][68];
    __shared__ float bse[12][68];
    __shared__ float bso[12][68];
    __shared__ int   mms[64];
    __shared__ int   mns[64];

    const int n0 = blockIdx.x * 64;
    const int m0 = blockIdx.y * 64;
    const int b  = blockIdx.z;
    const int tid  = threadIdx.x;
    const int lane = tid & 31;
    const int wid  = tid >> 5;
    const int mw = (wid >> 1) * 32;
    const int nw = (wid & 1) * 32;
    const uint32_t sqa = smem_u32(sq);
    const uint32_t ska = smem_u32(sk);

    const int lrow = tid >> 3;
    const int lch  = tid & 7;

    if (tid < 64)       mms[tid]      = mask[b*NN + m0 + tid];
    else if (tid < 128) mns[tid - 64] = mask[b*NN + n0 + tid - 64];

    const size_t ENT_SZ = (size_t)BB * 2 * NN * NN;

    const int ty = tid >> 4;
    const int tx = tid & 15;

    for (int t = 0; t < 3; t++) {
        const int H = (t == 0) ? 2 : 12;
        __syncthreads();
        #pragma unroll
        for (int i = 0; i < 4; i++) {
            const int row = lrow + i * 16;
            const uint32_t bo = sw128(row * 128 + lch * 16);
            *(uint4*)(sq + bo) = *(const uint4*)&g_q[t][b][m0 + row][lch * 8];
            *(uint4*)(sk + bo) = *(const uint4*)&g_k[t][b][n0 + row][lch * 8];
        }
        for (int f = tid; f < H * 64; f += 128) {
            const int hd = f >> 6, e = f & 63;
            bse[hd][e] = g_bias[t][b][2*hd][n0 + e];
            bso[hd][e] = g_bias[t][b][2*hd + 1][m0 + e];
        }
        __syncthreads();

        float acc[2][4][4] = {};
        #pragma unroll
        for (int ks = 0; ks < 4; ks++) {
            const int kb = ks * 32;
            uint32_t afr[2][4];
            #pragma unroll
            for (int f = 0; f < 2; f++) {
                const int row = mw + f * 16 + (lane & 15);
                ldmx4(afr[f], sqa + sw128(row * 128 + kb + ((lane >> 4) << 4)));
            }
            uint32_t bfr[4][2];
            #pragma unroll
            for (int g2 = 0; g2 < 2; g2++) {
                const int sel = lane >> 3;
                const int row = nw + g2 * 16 + ((sel & 2) ? 8 : 0) + (lane & 7);
                uint32_t tr[4];
                ldmx4(tr, ska + sw128(row * 128 + kb + ((sel & 1) << 4)));
                bfr[g2 * 2 + 0][0] = tr[0]; bfr[g2 * 2 + 0][1] = tr[1];
                bfr[g2 * 2 + 1][0] = tr[2]; bfr[g2 * 2 + 1][1] = tr[3];
            }
            #pragma unroll
            for (int f = 0; f < 2; f++)
                #pragma unroll
                for (int g = 0; g < 4; g++)
                    mma_bf16(acc[f][g], afr[f], bfr[g]);
        }

        #pragma unroll
        for (int f = 0; f < 2; f++) {
            const int r = mw + f * 16 + (lane >> 2);
            #pragma unroll
            for (int g = 0; g < 4; g++) {
                const int c = nw + g * 8 + (lane & 3) * 2;
                sf[r][c]     = acc[f][g][0];
                sf[r][c + 1] = acc[f][g][1];
                sf[r + 8][c]     = acc[f][g][2];
                sf[r + 8][c + 1] = acc[f][g][3];
            }
        }
        __syncthreads();

        int nj[4];
        #pragma unroll
        for (int j = 0; j < 4; j++) nj[j] = mns[tx*4 + j];

        float accm[8][4];
        #pragma unroll
        for (int i = 0; i < 8; i++) {
            const int r = ty*8 + i;
            const int mi = mms[r];
            float4 v = *(const float4*)&sf[r][tx*4];
            float* vv = &v.x;
            #pragma unroll
            for (int j = 0; j < 4; j++) {
                float sub = 0.0f;
                if (!(mi & nj[j])) sub = NEGF;
                if (t == 0 && (m0 + r) > (n0 + tx*4 + j)) sub += NEGF;
                accm[i][j] = vv[j] - sub;
            }
        }

        const size_t base = (t == 0) ? 0
                          : (t == 1) ? ENT_SZ
                                     : ENT_SZ + (size_t)BB*12*NN*NN;

        for (int hd = 0; hd < H; hd++) {
            float4 bev = *(const float4*)&bse[hd][tx*4];
            const float beo[4] = {bev.x, bev.y, bev.z, bev.w};
            float* op = out + base
                      + (((size_t)(b*H + hd)) * NN + (m0 + ty*8)) * NN
                      + n0 + tx*4;
            #pragma unroll
            for (int i = 0; i < 8; i++) {
                const float bo = bso[hd][ty*8 + i];
                float4 o;
                o.x = accm[i][0] + beo[0] + bo;
                o.y = accm[i][1] + beo[1] + bo;
                o.z = accm[i][2] + beo[2] + bo;
                o.w = accm[i][3] + beo[3] + bo;
                __stcs((float4*)(op + (size_t)i * NN), o);
            }
        }
    }
}

// =============================================================
extern "C" void kernel_launch(void* const* d_in, const int* in_sizes, int n_in,
                              void* d_out, int out_size)
{
    (void)in_sizes; (void)n_in; (void)out_size;
    const float* chars = (const float*)d_in[0];
    const int*   mask  = (const int*)  d_in[1];
    const float* w1e = (const float*)d_in[2];
    const float* b1e = (const float*)d_in[3];
    const float* w2e = (const float*)d_in[4];
    const float* b2e = (const float*)d_in[5];
    const float* w1h = (const float*)d_in[6];
    const float* b1h = (const float*)d_in[7];
    const float* w2h = (const float*)d_in[8];
    const float* b2h = (const float*)d_in[9];
    const float* w1t = (const float*)d_in[10];
    const float* b1t = (const float*)d_in[11];
    const float* w2t = (const float*)d_in[12];
    const float* b2t = (const float*)d_in[13];
    float* out = (float*)d_out;

    const int cvt_groups = XT_GROUPS + WT_GROUPS;
    k0_convert<<<(cvt_groups + 255) / 256, 256>>>(chars, w1e, w1h, w1t);

    dim3 g12(3, 64);
    k12_fused<<<g12, 256>>>(b1e, b1h, b1t, w2e, b2e, w2h, b2h, w2t, b2t);

    dim3 g3(8, 8, 8);
    k3_out<<<g3, 128>>>(mask, out);
}

// round 17
// speedup vs baseline: 2.5906x; 1.0242x over previous
#include <cuda_runtime.h>
#include <cuda_bf16.h>
#include <cstdint>

#define BB 8
#define NN 512
#define DD 768
#define HSZ 64
#define TOK (BB*NN)        // 4096
#define HDIM 384           // 3 * 128
#define NEGF 1e12f

// ---------------- scratch (no allocs allowed) ----------------
__device__ __nv_bfloat16 g_wb[HDIM*DD];           // w1 (ent|head|tail) in bf16
__device__ __nv_bfloat16 g_q[3][BB][NN][HSZ];     // bf16 q (scaled 1/8, rope'd)
__device__ __nv_bfloat16 g_k[3][BB][NN][HSZ];     // bf16 k
__device__ float g_bias[3][BB][24][NN];

__device__ __forceinline__ uint32_t smem_u32(const void* p) {
    uint32_t a;
    asm("{ .reg .u64 t; cvta.to.shared.u64 t, %1; cvt.u32.u64 %0, t; }" : "=r"(a) : "l"(p));
    return a;
}
__device__ __forceinline__ uint32_t sw128(uint32_t off) {
    return off ^ ((off >> 3) & 0x70);
}
__device__ __forceinline__ void ldmx4(uint32_t* r, uint32_t addr) {
    asm volatile("ldmatrix.sync.aligned.m8n8.x4.shared.b16 {%0,%1,%2,%3}, [%4];"
                 : "=r"(r[0]), "=r"(r[1]), "=r"(r[2]), "=r"(r[3]) : "r"(addr));
}
__device__ __forceinline__ void mma_bf16(float* d, const uint32_t* a, const uint32_t* b) {
    asm volatile(
        "mma.sync.aligned.m16n8k16.row.col.f32.bf16.bf16.f32 "
        "{%0,%1,%2,%3}, {%4,%5,%6,%7}, {%8,%9}, {%0,%1,%2,%3};"
        : "+f"(d[0]), "+f"(d[1]), "+f"(d[2]), "+f"(d[3])
        : "r"(a[0]), "r"(a[1]), "r"(a[2]), "r"(a[3]), "r"(b[0]), "r"(b[1]));
}
__device__ __forceinline__ uint4 pack_bf16x8(float4 a, float4 b) {
    __nv_bfloat162 p0 = __floats2bfloat162_rn(a.x, a.y);
    __nv_bfloat162 p1 = __floats2bfloat162_rn(a.z, a.w);
    __nv_bfloat162 p2 = __floats2bfloat162_rn(b.x, b.y);
    __nv_bfloat162 p3 = __floats2bfloat162_rn(b.z, b.w);
    uint4 r;
    r.x = *(uint32_t*)&p0; r.y = *(uint32_t*)&p1;
    r.z = *(uint32_t*)&p2; r.w = *(uint32_t*)&p3;
    return r;
}

// =============================================================
// Kernel 0w: fp32 -> bf16 convert for W1(ent|head|tail) only
// =============================================================
#define WT_GROUPS (HDIM*DD/8)     // 36864
__global__ __launch_bounds__(256) void k0w_convert(
    const float* __restrict__ w1e, const float* __restrict__ w1h,
    const float* __restrict__ w1t)
{
    const int i = blockIdx.x * 256 + threadIdx.x;
    if (i >= WT_GROUPS) return;
    const int n = (i * 8) / DD;
    const int col = (i * 8) % DD;
    const int br = n >> 7, nl = n & 127;
    const float* w = (br == 0) ? w1e : (br == 1) ? w1h : w1t;
    const float* src = w + (size_t)nl * DD + col;
    float4 a = *(const float4*)src;
    float4 b = *(const float4*)(src + 4);
    *(uint4*)(g_wb + (size_t)n * DD + col) = pack_bf16x8(a, b);
}

// =============================================================
// Kernel 12 (fused k1+k2): per (type, 64-row tile):
//   h[64][128] = X @ W1_t^T + b1_t  (HMMA, X converted fp32->bf16 inline)
//   -> q/k deinterleave (+RoPE for ent) -> bf16 g_q/g_k
//   -> bias GEMV (warp-per-weight-row, broadcast weights) -> g_bias
// =============================================================
__global__ __launch_bounds__(256) void k12_fused(
    const float* __restrict__ X,
    const float* __restrict__ b1e, const float* __restrict__ b1h,
    const float* __restrict__ b1t,
    const float* __restrict__ w2e, const float* __restrict__ b2e,
    const float* __restrict__ w2h, const float* __restrict__ b2h,
    const float* __restrict__ w2t, const float* __restrict__ b2t)
{
    // buf: GEMM phase = sA (8KB) | sB (16KB); prep phase = sf[64][133] fp32
    __shared__ __align__(128) uint8_t buf[64 * 133 * 4];   // 34048 B
    __shared__ float w2s[24][129];
    __shared__ float b1s[128];
    __shared__ float b2s[24];
    __shared__ float invs[32];

    uint8_t* sA = buf;                // 64 rows x 128B
    uint8_t* sB = buf + 8192;         // 128 rows x 128B
    float (*sf)[133] = (float(*)[133])buf;

    const int tid  = threadIdx.x;
    const int lane = tid & 31;
    const int wid  = tid >> 5;
    const int t  = blockIdx.x;        // type 0..2
    const int mt = blockIdx.y;        // 0..63
    const int m0 = mt * 64;
    const int H2 = (t == 0) ? 2 : 12;

    const uint32_t sa = smem_u32(sA);
    const uint32_t sb = smem_u32(sB);

    const int mw = (wid >> 2) * 32;   // 2 row groups
    const int nw = (wid & 3) * 32;    // 4 col groups

    // stage small params
    const float* b1 = (t == 0) ? b1e : (t == 1) ? b1h : b1t;
    const float* w2 = (t == 0) ? w2e : (t == 1) ? w2h : w2t;
    const float* b2 = (t == 0) ? b2e : (t == 1) ? b2h : b2t;
    if (tid < 128) b1s[tid] = b1[tid];
    if (tid < 24 && tid < 2*H2) b2s[tid] = b2[tid];
    if (tid < 32) invs[tid] = exp2f(-(float)tid * 0.4152410118609203f); // 10000^(-i/32)
    for (int f = tid; f < 2*H2*128; f += 256) {
        const int r = f >> 7, e = f & 127;
        w2s[r][e] = w2[r*128 + e];
    }

    // per-thread staging map: lin = i*256 + tid; row = lin>>3, ch = lin&7
    const int srow = tid >> 3;
    const int sch  = tid & 7;

    // ---------------- GEMM: 64x128, K=768 ----------------
    float acc[2][4][4] = {};
    float4 a0[2], a1[2];
    uint4 br[4];
    {
        #pragma unroll
        for (int i = 0; i < 2; i++) {
            const int row = srow + i * 32;
            const float* xg = X + (size_t)(m0 + row) * DD + sch * 8;
            a0[i] = *(const float4*)xg;
            a1[i] = *(const float4*)(xg + 4);
        }
        #pragma unroll
        for (int i = 0; i < 4; i++) {
            const int row = srow + i * 32;
            br[i] = *(const uint4*)(g_wb + (size_t)(t * 128 + row) * DD + sch * 8);
        }
    }

    for (int c = 0; c < 12; c++) {
        __syncthreads();
        #pragma unroll
        for (int i = 0; i < 2; i++) {
            const int row = srow + i * 32;
            *(uint4*)(sA + sw128(row * 128 + sch * 16)) = pack_bf16x8(a0[i], a1[i]);
        }
        #pragma unroll
        for (int i = 0; i < 4; i++) {
            const int row = srow + i * 32;
            *(uint4*)(sB + sw128(row * 128 + sch * 16)) = br[i];
        }
        __syncthreads();
        if (c < 11) {
            const int cc = c + 1;
            #pragma unroll
            for (int i = 0; i < 2; i++) {
                const int row = srow + i * 32;
                const float* xg = X + (size_t)(m0 + row) * DD + cc * 64 + sch * 8;
                a0[i] = *(const float4*)xg;
                a1[i] = *(const float4*)(xg + 4);
            }
            #pragma unroll
            for (int i = 0; i < 4; i++) {
                const int row = srow + i * 32;
                br[i] = *(const uint4*)(g_wb + (size_t)(t * 128 + row) * DD + cc * 64 + sch * 8);
            }
        }
        #pragma unroll
        for (int ks = 0; ks < 4; ks++) {
            const int kb = ks * 32;
            uint32_t afr[2][4];
            #pragma unroll
            for (int f = 0; f < 2; f++) {
                const int row = mw + f * 16 + (lane & 15);
                ldmx4(afr[f], sa + sw128(row * 128 + kb + ((lane >> 4) << 4)));
            }
            uint32_t bfr[4][2];
            #pragma unroll
            for (int g2 = 0; g2 < 2; g2++) {
                const int sel = lane >> 3;
                const int row = nw + g2 * 16 + ((sel & 2) ? 8 : 0) + (lane & 7);
                uint32_t tr[4];
                ldmx4(tr, sb + sw128(row * 128 + kb + ((sel & 1) << 4)));
                bfr[g2 * 2 + 0][0] = tr[0]; bfr[g2 * 2 + 0][1] = tr[1];
                bfr[g2 * 2 + 1][0] = tr[2]; bfr[g2 * 2 + 1][1] = tr[3];
            }
            #pragma unroll
            for (int f = 0; f < 2; f++)
                #pragma unroll
                for (int g = 0; g < 4; g++)
                    mma_bf16(acc[f][g], afr[f], bfr[g]);
        }
    }
    __syncthreads();   // all warps done reading sA/sB before sf overwrite

    // fragments + b1 -> sf
    #pragma unroll
    for (int f = 0; f < 2; f++) {
        const int r = mw + f * 16 + (lane >> 2);
        #pragma unroll
        for (int g = 0; g < 4; g++) {
            const int cidx = nw + g * 8 + (lane & 3) * 2;
            sf[r][cidx]     = acc[f][g][0] + b1s[cidx];
            sf[r][cidx + 1] = acc[f][g][1] + b1s[cidx + 1];
            sf[r + 8][cidx]     = acc[f][g][2] + b1s[cidx];
            sf[r + 8][cidx + 1] = acc[f][g][3] + b1s[cidx + 1];
        }
    }
    __syncthreads();

    // ---------------- q/k deinterleave (+RoPE) ----------------
    #pragma unroll
    for (int it = 0; it < 8; it++) {
        const int lin = it * 256 + tid;
        const int r = lin >> 5, p = lin & 31;
        const int tok = m0 + r;
        const int b = tok >> 9, n = tok & 511;
        float q0 = sf[r][4*p],     q1 = sf[r][4*p + 2];
        float k0 = sf[r][4*p + 1], k1 = sf[r][4*p + 3];
        if (t == 0) {
            const float ang = (float)n * invs[p];
            float s, cth;
            sincosf(ang, &s, &cth);
            const float nq0 = q0*cth - q1*s, nq1 = q1*cth + q0*s;
            const float nk0 = k0*cth - k1*s, nk1 = k1*cth + k0*s;
            q0 = nq0; q1 = nq1; k0 = nk0; k1 = nk1;
        }
        __nv_bfloat162 qv = __floats2bfloat162_rn(q0 * 0.125f, q1 * 0.125f);
        __nv_bfloat162 kv = __floats2bfloat162_rn(k0, k1);
        *(__nv_bfloat162*)&g_q[t][b][n][2*p] = qv;
        *(__nv_bfloat162*)&g_k[t][b][n][2*p] = kv;
    }

    // ---------------- bias GEMV (warp-per-weight-row) ----------------
    // pair = (j, half): warp handles weight row j for 32 tokens.
    // w2s[j][e] is a same-address broadcast across the warp (free);
    // sf row stride 133 (gcd(5,32)=1) keeps h loads conflict-free.
    const int npairs = 2 * H2 * 2;   // 8 (ent) or 48 (head/tail)
    for (int pair = wid; pair < npairs; pair += 8) {
        const int j = pair >> 1;
        const int r = (pair & 1) * 32 + lane;
        const int tok = m0 + r;
        const int b = tok >> 9, n = tok & 511;
        const float* hb = sf[r];
        const float* wr = w2s[j];
        float s0 = 0, s1 = 0, s2 = 0, s3 = 0;
        #pragma unroll
        for (int e = 0; e < 128; e += 4) {
            s0 += hb[e]   * wr[e];
            s1 += hb[e+1] * wr[e+1];
            s2 += hb[e+2] * wr[e+2];
            s3 += hb[e+3] * wr[e+3];
        }
        g_bias[t][b][j][n] = ((s0 + s1) + (s2 + s3) + b2s[j]) * 0.5f;
    }
}

// =============================================================
// Kernel 3 (R8 config): per (b, 64x64 tile): QK^T via bf16 mma
// once per type, mask folded once, 26-plane fan-out, stcs.
// 128 threads / 4 warps.
// =============================================================
__global__ __launch_bounds__(128) void k3_out(
    const int* __restrict__ mask, float* __restrict__ out)
{
    __shared__ __align__(128) uint8_t sq[64 * 128];
    __shared__ __align__(128) uint8_t sk[64 * 128];
    __shared__ float sf[64][68];
    __shared__ float bse[12][68];
    __shared__ float bso[12][68];
    __shared__ int   mms[64];
    __shared__ int   mns[64];

    const int n0 = blockIdx.x * 64;
    const int m0 = blockIdx.y * 64;
    const int b  = blockIdx.z;
    const int tid  = threadIdx.x;
    const int lane = tid & 31;
    const int wid  = tid >> 5;
    const int mw = (wid >> 1) * 32;
    const int nw = (wid & 1) * 32;
    const uint32_t sqa = smem_u32(sq);
    const uint32_t ska = smem_u32(sk);

    const int lrow = tid >> 3;
    const int lch  = tid & 7;

    if (tid < 64)       mms[tid]      = mask[b*NN + m0 + tid];
    else if (tid < 128) mns[tid - 64] = mask[b*NN + n0 + tid - 64];

    const size_t ENT_SZ = (size_t)BB * 2 * NN * NN;

    const int ty = tid >> 4;
    const int tx = tid & 15;

    for (int t = 0; t < 3; t++) {
        const int H = (t == 0) ? 2 : 12;
        __syncthreads();
        #pragma unroll
        for (int i = 0; i < 4; i++) {
            const int row = lrow + i * 16;
            const uint32_t bo = sw128(row * 128 + lch * 16);
            *(uint4*)(sq + bo) = *(const uint4*)&g_q[t][b][m0 + row][lch * 8];
            *(uint4*)(sk + bo) = *(const uint4*)&g_k[t][b][n0 + row][lch * 8];
        }
        for (int f = tid; f < H * 64; f += 128) {
            const int hd = f >> 6, e = f & 63;
            bse[hd][e] = g_bias[t][b][2*hd][n0 + e];
            bso[hd][e] = g_bias[t][b][2*hd + 1][m0 + e];
        }
        __syncthreads();

        float acc[2][4][4] = {};
        #pragma unroll
        for (int ks = 0; ks < 4; ks++) {
            const int kb = ks * 32;
            uint32_t afr[2][4];
            #pragma unroll
            for (int f = 0; f < 2; f++) {
                const int row = mw + f * 16 + (lane & 15);
                ldmx4(afr[f], sqa + sw128(row * 128 + kb + ((lane >> 4) << 4)));
            }
            uint32_t bfr[4][2];
            #pragma unroll
            for (int g2 = 0; g2 < 2; g2++) {
                const int sel = lane >> 3;
                const int row = nw + g2 * 16 + ((sel & 2) ? 8 : 0) + (lane & 7);
                uint32_t tr[4];
                ldmx4(tr, ska + sw128(row * 128 + kb + ((sel & 1) << 4)));
                bfr[g2 * 2 + 0][0] = tr[0]; bfr[g2 * 2 + 0][1] = tr[1];
                bfr[g2 * 2 + 1][0] = tr[2]; bfr[g2 * 2 + 1][1] = tr[3];
            }
            #pragma unroll
            for (int f = 0; f < 2; f++)
                #pragma unroll
                for (int g = 0; g < 4; g++)
                    mma_bf16(acc[f][g], afr[f], bfr[g]);
        }

        #pragma unroll
        for (int f = 0; f < 2; f++) {
            const int r = mw + f * 16 + (lane >> 2);
            #pragma unroll
            for (int g = 0; g < 4; g++) {
                const int c = nw + g * 8 + (lane & 3) * 2;
                sf[r][c]     = acc[f][g][0];
                sf[r][c + 1] = acc[f][g][1];
                sf[r + 8][c]     = acc[f][g][2];
                sf[r + 8][c + 1] = acc[f][g][3];
            }
        }
        __syncthreads();

        int nj[4];
        #pragma unroll
        for (int j = 0; j < 4; j++) nj[j] = mns[tx*4 + j];

        float accm[8][4];
        #pragma unroll
        for (int i = 0; i < 8; i++) {
            const int r = ty*8 + i;
            const int mi = mms[r];
            float4 v = *(const float4*)&sf[r][tx*4];
            float* vv = &v.x;
            #pragma unroll
            for (int j = 0; j < 4; j++) {
                float sub = 0.0f;
                if (!(mi & nj[j])) sub = NEGF;
                if (t == 0 && (m0 + r) > (n0 + tx*4 + j)) sub += NEGF;
                accm[i][j] = vv[j] - sub;
            }
        }

        const size_t base = (t == 0) ? 0
                          : (t == 1) ? ENT_SZ
                                     : ENT_SZ + (size_t)BB*12*NN*NN;

        for (int hd = 0; hd < H; hd++) {
            float4 bev = *(const float4*)&bse[hd][tx*4];
            const float beo[4] = {bev.x, bev.y, bev.z, bev.w};
            float* op = out + base
                      + (((size_t)(b*H + hd)) * NN + (m0 + ty*8)) * NN
                      + n0 + tx*4;
            #pragma unroll
            for (int i = 0; i < 8; i++) {
                const float bo = bso[hd][ty*8 + i];
                float4 o;
                o.x = accm[i][0] + beo[0] + bo;
                o.y = accm[i][1] + beo[1] + bo;
                o.z = accm[i][2] + beo[2] + bo;
                o.w = accm[i][3] + beo[3] + bo;
                __stcs((float4*)(op + (size_t)i * NN), o);
            }
        }
    }
}

// =============================================================
extern "C" void kernel_launch(void* const* d_in, const int* in_sizes, int n_in,
                              void* d_out, int out_size)
{
    (void)in_sizes; (void)n_in; (void)out_size;
    const float* chars = (const float*)d_in[0];
    const int*   mask  = (const int*)  d_in[1];
    const float* w1e = (const float*)d_in[2];
    const float* b1e = (const float*)d_in[3];
    const float* w2e = (const float*)d_in[4];
    const float* b2e = (const float*)d_in[5];
    const float* w1h = (const float*)d_in[6];
    const float* b1h = (const float*)d_in[7];
    const float* w2h = (const float*)d_in[8];
    const float* b2h = (const float*)d_in[9];
    const float* w1t = (const float*)d_in[10];
    const float* b1t = (const float*)d_in[11];
    const float* w2t = (const float*)d_in[12];
    const float* b2t = (const float*)d_in[13];
    float* out = (float*)d_out;

    k0w_convert<<<(WT_GROUPS + 255) / 256, 256>>>(w1e, w1h, w1t);

    dim3 g12(3, 64);
    k12_fused<<<g12, 256>>>(chars, b1e, b1h, b1t, w2e, b2e, w2h, b2h, w2t, b2t);

    dim3 g3(8, 8, 8);
    k3_out<<<g3, 128>>>(mask, out);
}